// round 8
// baseline (speedup 1.0000x reference)
#include <cuda_runtime.h>
#include <cuda_bf16.h>
#include <cstdint>
#include <cstddef>

// Problem constants
#define T_STEPS 784
#define NBATCH  128
#define HID     512
#define OUTC    10
#define DECAY   0.2f
#define THRESH  0.5f
#define KDIM    512

// GEMM tiling
#define BM 128
#define BN 128
#define BK 64
#define ROWB 144u              // smem bytes per row: 64 bf16 (128B) + 16B pad
#define TILEB (128u * ROWB)    // 18432 B
#define STAGEB (3u * TILEB)    // A + Wh + Wl per stage
#define GEMM_SMEM (2u * STAGEB + 512u)  // + jrow[128] ints

// Recurrence pipelining
#define UNR 16                 // 784 = 49 * 16
#define NBLK (T_STEPS / UNR)   // 49

#define SEQ_ELEMS ((size_t)T_STEPS * NBATCH * HID)
__device__ __nv_bfloat16 g_S1b[SEQ_ELEMS];   // layer-1 spikes [t][n][i] (exact 0/1)
__device__ __nv_bfloat16 g_S2b[SEQ_ELEMS];   // layer-2 spikes
__device__ float         g_C  [SEQ_ELEMS];   // GEMM output, COMPACTED: [t][n][pos]
__device__ __nv_bfloat16 g_W2h[HID*HID], g_W2l[HID*HID];
__device__ __nv_bfloat16 g_W3h[HID*HID], g_W3l[HID*HID];
__device__ float         g_maskT[3][T_STEPS * HID];   // transposed masks [T][H]
// N-compaction metadata (l=0: mask2, l=1: mask3)
__device__ int g_jl [2][T_STEPS * HID];   // active j list per t
__device__ int g_cnt[2][T_STEPS];         // active count per t
__device__ int g_pos[2][T_STEPS * HID];   // per (t,j): pos if active else -1

// ---------------------------------------------------------------------------
// PTX helpers
// ---------------------------------------------------------------------------
__device__ __forceinline__ uint32_t smem_u32(const void* p){
    uint32_t a;
    asm("{ .reg .u64 t; cvta.to.shared.u64 t, %1; cvt.u32.u64 %0, t; }" : "=r"(a) : "l"(p));
    return a;
}
__device__ __forceinline__ void cp16(uint32_t saddr, const void* gaddr){
    asm volatile("cp.async.cg.shared.global [%0], [%1], 16;" :: "r"(saddr), "l"(gaddr));
}
__device__ __forceinline__ void ldsm4(uint32_t* r, uint32_t addr){
    asm volatile("ldmatrix.sync.aligned.m8n8.x4.shared.b16 {%0,%1,%2,%3}, [%4];"
        : "=r"(r[0]), "=r"(r[1]), "=r"(r[2]), "=r"(r[3]) : "r"(addr));
}
__device__ __forceinline__ void mma_bf16(float* c, const uint32_t* a, const uint32_t* b){
    asm volatile(
        "mma.sync.aligned.m16n8k16.row.col.f32.bf16.bf16.f32 "
        "{%0,%1,%2,%3}, {%4,%5,%6,%7}, {%8,%9}, {%0,%1,%2,%3};"
        : "+f"(c[0]), "+f"(c[1]), "+f"(c[2]), "+f"(c[3])
        : "r"(a[0]), "r"(a[1]), "r"(a[2]), "r"(a[3]), "r"(b[0]), "r"(b[1]));
}

// ---------------------------------------------------------------------------
// Weight split: W -> hi(bf16) + lo(bf16)
// ---------------------------------------------------------------------------
__global__ void split_kernel(const float* __restrict__ W2, const float* __restrict__ W3){
    int idx = blockIdx.x * blockDim.x + threadIdx.x;
    if (idx < HID * HID){
        float w = W2[idx];
        __nv_bfloat16 h = __float2bfloat16(w);
        g_W2h[idx] = h;
        g_W2l[idx] = __float2bfloat16(w - __bfloat162float(h));
        w = W3[idx];
        h = __float2bfloat16(w);
        g_W3h[idx] = h;
        g_W3l[idx] = __float2bfloat16(w - __bfloat162float(h));
    }
}

// ---------------------------------------------------------------------------
// Mask transpose: [H][T] -> [T][H]  (layer1 still reads mask floats)
// ---------------------------------------------------------------------------
__global__ void maskT_kernel(const float* __restrict__ m1,
                             const float* __restrict__ m2,
                             const float* __restrict__ m3)
{
    __shared__ float tile[32][33];
    const float* src = (blockIdx.z == 0) ? m1 : (blockIdx.z == 1) ? m2 : m3;
    const int jb = blockIdx.x * 32;
    const int tb = blockIdx.y * 32;
    const int tx = threadIdx.x, ty = threadIdx.y;

    if (tb + tx < T_STEPS)
        tile[ty][tx] = src[(size_t)(jb + ty) * T_STEPS + tb + tx];
    __syncthreads();
    if (tb + ty < T_STEPS)
        g_maskT[blockIdx.z][(size_t)(tb + ty) * HID + jb + tx] = tile[tx][ty];
}

// ---------------------------------------------------------------------------
// Active-column compaction: per (t, mask) prefix-scan -> jlist, count, pos.
// grid (T_STEPS, 2), block HID.
// ---------------------------------------------------------------------------
__global__ void compact_kernel(const float* __restrict__ m2,
                               const float* __restrict__ m3)
{
    const int t = blockIdx.x;
    const int l = blockIdx.y;
    const float* __restrict__ src = l ? m3 : m2;
    const int j = threadIdx.x;
    __shared__ int scan[HID];

    const int on = (src[(size_t)j * T_STEPS + t] != 0.f) ? 1 : 0;
    int v = on;
    scan[j] = v;
    __syncthreads();
    #pragma unroll
    for (int o = 1; o < HID; o <<= 1){
        const int add = (j >= o) ? scan[j - o] : 0;
        __syncthreads();
        v += add;
        scan[j] = v;
        __syncthreads();
    }
    if (on) g_jl[l][t * HID + (v - 1)] = j;
    g_pos[l][t * HID + j] = on ? (v - 1) : -1;
    if (j == HID - 1) g_cnt[l][t] = v;
}

// ---------------------------------------------------------------------------
// Layer-1 recurrence, 16-step register double-buffer.
// ---------------------------------------------------------------------------
__global__ void layer1_kernel(const float* __restrict__ x,
                              const float* __restrict__ W1,
                              const float* __restrict__ b1,
                              float* __restrict__ fr1)
{
    const int n = blockIdx.x;
    const int i = blockIdx.y * 128 + threadIdx.x;
    const float w = W1[i];
    const float b = b1[i];
    const float* __restrict__ xr = x + (size_t)n * T_STEPS;
    const float* __restrict__ mk = g_maskT[0];
    __nv_bfloat16* __restrict__ sOut = g_S1b + (size_t)n * HID + i;
    const size_t cstr = (size_t)NBATCH * HID;

    float xb[2][UNR], mb[2][UNR];
    #pragma unroll
    for (int u = 0; u < UNR; ++u){
        xb[0][u] = xr[u];
        mb[0][u] = mk[(size_t)u * HID + i];
    }

    float mem = 0.f, spike = 0.f, ss = 0.f;
    for (int tc = 0; tc < NBLK; ++tc){
        const int cur = tc & 1, nxt = cur ^ 1;
        const int tb = tc * UNR;
        if (tc + 1 < NBLK){
            #pragma unroll
            for (int u = 0; u < UNR; ++u){
                xb[nxt][u] = xr[tb + UNR + u];
                mb[nxt][u] = mk[(size_t)(tb + UNR + u) * HID + i];
            }
        }
        #pragma unroll
        for (int u = 0; u < UNR; ++u){
            const float m_t = mb[cur][u];
            const float new_mem = mem * DECAY * (1.f - spike) + xb[cur][u] * w + b;
            if (m_t != 0.f) mem = new_mem;
            const float spk = (mem > THRESH) ? m_t : 0.f;
            sOut[(size_t)(tb + u) * cstr] = __float2bfloat16(spk);
            ss += spk;
            spike = spk;
        }
    }
    fr1[n * HID + i] = ss * (1.f / (float)T_STEPS);
}

// ---------------------------------------------------------------------------
// bf16 HMMA GEMM, N-compacted with COMPACTED output: per timestep t, compute
// only active columns; store Cc[t][n][pos] (contiguous in pos -> coalesced).
// ---------------------------------------------------------------------------
__global__ void __launch_bounds__(256, 2)
gemm_bf16(int which)
{
    extern __shared__ char smem[];
    const int t = blockIdx.y;
    const int cnt = g_cnt[which][t];
    const int n0 = blockIdx.x * BN;          // pos-space tile base
    if (n0 >= cnt) return;

    const __nv_bfloat16* __restrict__ A  = which ? g_S2b : g_S1b;
    const __nv_bfloat16* __restrict__ Bh = which ? g_W3h : g_W2h;
    const __nv_bfloat16* __restrict__ Bl = which ? g_W3l : g_W2l;
    const int* __restrict__ jl = g_jl[which] + t * HID + n0;

    const uint32_t sb = smem_u32(smem);
    int* jrow_s = (int*)(smem + 2u * STAGEB);
    const int tid  = threadIdx.x;
    const int lane = tid & 31;
    const int wrp  = tid >> 5;
    const int wm   = wrp & 1;          // 2 warp-rows of 64
    const int wn   = wrp >> 1;         // 4 warp-cols of 32
    const int m0 = t * BM;             // rows = (t, n=0..127)
    const int climit = cnt - n0;       // valid local positions

    if (tid < 128) jrow_s[tid] = (tid < climit) ? jl[tid] : 0;
    __syncthreads();

    auto load_stage = [&](int st, int c){
        const uint32_t base = sb + (uint32_t)st * STAGEB;
        #pragma unroll
        for (int i = 0; i < 4; ++i){
            const int q   = tid + 256 * i;
            const int row = q >> 3;
            const int kc  = q & 7;
            const uint32_t soff = (uint32_t)row * ROWB + (uint32_t)kc * 16u;
            const size_t gk = (size_t)c * BK + (size_t)kc * 8;
            const int jr = jrow_s[row];
            cp16(base + soff,             A  + (size_t)(m0 + row) * KDIM + gk);
            cp16(base + TILEB + soff,     Bh + (size_t)jr * KDIM + gk);
            cp16(base + 2u*TILEB + soff,  Bl + (size_t)jr * KDIM + gk);
        }
        asm volatile("cp.async.commit_group;" ::: "memory");
    };

    float acc[4][4][4];
    #pragma unroll
    for (int mi = 0; mi < 4; ++mi)
        #pragma unroll
        for (int ni = 0; ni < 4; ++ni)
            #pragma unroll
            for (int q = 0; q < 4; ++q) acc[mi][ni][q] = 0.f;

    const uint32_t aOff = (uint32_t)(wm * 64 + (lane & 15)) * ROWB
                        + (uint32_t)((lane >> 4) << 3) * 2u;
    const uint32_t bOff = (uint32_t)(wn * 32 + ((lane >> 4) << 3) + (lane & 7)) * ROWB
                        + (uint32_t)(((lane >> 3) & 1) << 4);

    load_stage(0, 0);

    const int NC = KDIM / BK;   // 8
    for (int c = 0; c < NC; ++c){
        if (c + 1 < NC){
            load_stage((c + 1) & 1, c + 1);
            asm volatile("cp.async.wait_group 1;" ::: "memory");
        } else {
            asm volatile("cp.async.wait_group 0;" ::: "memory");
        }
        __syncthreads();

        const uint32_t base = sb + (uint32_t)(c & 1) * STAGEB;
        const uint32_t aB = base + aOff;
        const uint32_t hB = base + TILEB + bOff;
        const uint32_t lB = base + 2u*TILEB + bOff;

        #pragma unroll
        for (int k16 = 0; k16 < 4; ++k16){
            uint32_t a[4][4], bh[2][4], bl[2][4];
            #pragma unroll
            for (int mi = 0; mi < 4; ++mi)
                ldsm4(a[mi], aB + (uint32_t)(mi * 16) * ROWB + (uint32_t)k16 * 32u);
            #pragma unroll
            for (int p = 0; p < 2; ++p){
                ldsm4(bh[p], hB + (uint32_t)(p * 16) * ROWB + (uint32_t)k16 * 32u);
                ldsm4(bl[p], lB + (uint32_t)(p * 16) * ROWB + (uint32_t)k16 * 32u);
            }
            #pragma unroll
            for (int mi = 0; mi < 4; ++mi)
                #pragma unroll
                for (int ni = 0; ni < 4; ++ni){
                    mma_bf16(acc[mi][ni], a[mi], &bh[ni >> 1][(ni & 1) * 2]);
                    mma_bf16(acc[mi][ni], a[mi], &bl[ni >> 1][(ni & 1) * 2]);
                }
        }
        __syncthreads();
    }

    // Compacted epilogue: column = pos (n0 + local), contiguous float2 stores.
    const int rloc = wm * 64 + (lane >> 2);
    const int pbase = n0 + wn * 32 + (lane & 3) * 2;
    #pragma unroll
    for (int mi = 0; mi < 4; ++mi){
        float* row0 = g_C + (size_t)(m0 + rloc + mi * 16) * HID;
        float* row1 = row0 + 8 * HID;
        #pragma unroll
        for (int ni = 0; ni < 4; ++ni){
            const int p = pbase + ni * 8;
            if (p < cnt){
                if (p + 1 < cnt){
                    *(float2*)(row0 + p) = make_float2(acc[mi][ni][0], acc[mi][ni][1]);
                    *(float2*)(row1 + p) = make_float2(acc[mi][ni][2], acc[mi][ni][3]);
                } else {
                    row0[p] = acc[mi][ni][0];
                    row1[p] = acc[mi][ni][2];
                }
            }
        }
    }
}

// ---------------------------------------------------------------------------
// Layer-2/3 recurrence on COMPACTED C. pos table gives both the mask gate
// (pos>=0 <-> mask==1.0) and the gather index. pos prefetched 2 blocks ahead,
// c values 1 block ahead (c-load depends on pos).
// ---------------------------------------------------------------------------
__global__ void layerR_kernel(const float* __restrict__ bvec,
                              float* __restrict__ fr,
                              int posSel, int layer)
{
    const int n = blockIdx.x;
    const int j = blockIdx.y * 128 + threadIdx.x;
    const float bj = bvec[j];
    const int* __restrict__ pp = g_pos[posSel] + j;            // stride HID per t
    const float* __restrict__ cc = g_C + (size_t)n * HID;      // + t*cstr + pos
    const size_t cstr = (size_t)NBATCH * HID;
    __nv_bfloat16* __restrict__ sOut = g_S2b + (size_t)n * HID + j;

    int   pb[3][UNR];
    float cb[2][UNR];

    // Prefetch pos for blocks 0,1; c for block 0.
    #pragma unroll
    for (int u = 0; u < UNR; ++u) pb[0][u] = pp[(size_t)u * HID];
    #pragma unroll
    for (int u = 0; u < UNR; ++u) pb[1][u] = pp[(size_t)(UNR + u) * HID];
    #pragma unroll
    for (int u = 0; u < UNR; ++u){
        const int p = pb[0][u];
        cb[0][u] = (p >= 0) ? cc[(size_t)u * cstr + p] : 0.f;
    }

    float mem = 0.f, spike = 0.f, ss = 0.f;
    for (int tc = 0; tc < NBLK; ++tc){
        const int cs = tc & 1;
        const int tb = tc * UNR;
        if (tc + 2 < NBLK){
            const int s2 = (tc + 2) % 3;
            #pragma unroll
            for (int u = 0; u < UNR; ++u)
                pb[s2][u] = pp[(size_t)(tb + 2 * UNR + u) * HID];
        }
        if (tc + 1 < NBLK){
            const int s1 = (tc + 1) % 3;
            #pragma unroll
            for (int u = 0; u < UNR; ++u){
                const int p = pb[s1][u];
                cb[cs ^ 1][u] = (p >= 0) ? cc[(size_t)(tb + UNR + u) * cstr + p] : 0.f;
            }
        }
        const int s0 = tc % 3;
        #pragma unroll
        for (int u = 0; u < UNR; ++u){
            const bool on = (pb[s0][u] >= 0);
            const float new_mem = mem * DECAY * (1.f - spike) + cb[cs][u] + bj;
            if (on) mem = new_mem;
            const float spk = (mem > THRESH && on) ? 1.f : 0.f;
            if (layer == 2) sOut[(size_t)(tb + u) * cstr] = __float2bfloat16(spk);
            ss += spk;
            spike = spk;
        }
    }
    fr[n * HID + j] = ss * (1.f / (float)T_STEPS);
}

// ---------------------------------------------------------------------------
// Head: outputs[n][oc] = fr3[n] . W4[oc] + b4[oc]
// ---------------------------------------------------------------------------
__global__ void head_kernel(const float* __restrict__ fr3,
                            const float* __restrict__ W4,
                            const float* __restrict__ b4,
                            float* __restrict__ outputs)
{
    const int n = blockIdx.x;
    const int warp = threadIdx.x >> 5;
    const int lane = threadIdx.x & 31;
    const float* __restrict__ f = fr3 + (size_t)n * HID;
    const float* __restrict__ w = W4 + (size_t)warp * HID;
    float s = 0.f;
    for (int j = lane; j < HID; j += 32) s += f[j] * w[j];
#pragma unroll
    for (int o = 16; o > 0; o >>= 1) s += __shfl_xor_sync(0xffffffffu, s, o);
    if (lane == 0) outputs[n * OUTC + warp] = s + b4[warp];
}

// ---------------------------------------------------------------------------
// layer_fr[l] = mean(fr_l)
// ---------------------------------------------------------------------------
__global__ void lfr_kernel(const float* __restrict__ fr_all,
                           float* __restrict__ out3)
{
    const int l = blockIdx.x;
    const float* __restrict__ f = fr_all + (size_t)l * (NBATCH * HID);
    __shared__ float sh[256];
    float s = 0.f;
    for (int idx = threadIdx.x; idx < NBATCH * HID; idx += 256) s += f[idx];
    sh[threadIdx.x] = s;
    __syncthreads();
    for (int o = 128; o > 0; o >>= 1) {
        if (threadIdx.x < o) sh[threadIdx.x] += sh[threadIdx.x + o];
        __syncthreads();
    }
    if (threadIdx.x == 0) out3[l] = sh[0] * (1.f / (float)(NBATCH * HID));
}

// ---------------------------------------------------------------------------
// Launch
// ---------------------------------------------------------------------------
extern "C" void kernel_launch(void* const* d_in, const int* in_sizes, int n_in,
                              void* d_out, int out_size)
{
    const float* x     = (const float*)d_in[0];
    const float* W1    = (const float*)d_in[1];
    const float* b1    = (const float*)d_in[2];
    const float* W2    = (const float*)d_in[3];
    const float* b2    = (const float*)d_in[4];
    const float* W3    = (const float*)d_in[5];
    const float* b3    = (const float*)d_in[6];
    const float* W4    = (const float*)d_in[7];
    const float* b4    = (const float*)d_in[8];
    const float* mask1 = (const float*)d_in[9];
    const float* mask2 = (const float*)d_in[10];
    const float* mask3 = (const float*)d_in[11];

    float* out     = (float*)d_out;
    float* outputs = out;
    float* fr1     = out + NBATCH * OUTC;
    float* fr2     = fr1 + NBATCH * HID;
    float* fr3     = fr2 + NBATCH * HID;
    float* lfr     = fr3 + NBATCH * HID;

    cudaFuncSetAttribute(gemm_bf16, cudaFuncAttributeMaxDynamicSharedMemorySize, GEMM_SMEM);

    dim3 gemm_grid(4, T_STEPS);       // x = pos-tile (early-exit past cnt), y = t
    dim3 rec_grid(NBATCH, HID / 128); // 512 CTAs, 128 threads
    dim3 mt_grid(HID / 32, (T_STEPS + 31) / 32, 3);

    maskT_kernel<<<mt_grid, dim3(32, 32)>>>(mask1, mask2, mask3);
    split_kernel<<<(HID*HID + 255)/256, 256>>>(W2, W3);
    compact_kernel<<<dim3(T_STEPS, 2), HID>>>(mask2, mask3);
    layer1_kernel<<<rec_grid, 128>>>(x, W1, b1, fr1);
    gemm_bf16<<<gemm_grid, 256, GEMM_SMEM>>>(0);
    layerR_kernel<<<rec_grid, 128>>>(b2, fr2, 0, 2);
    gemm_bf16<<<gemm_grid, 256, GEMM_SMEM>>>(1);
    layerR_kernel<<<rec_grid, 128>>>(b3, fr3, 1, 3);
    head_kernel<<<NBATCH, 320>>>(fr3, W4, b4, outputs);
    lfr_kernel<<<3, 256>>>(fr1, lfr);
}

// round 9
// speedup vs baseline: 1.5063x; 1.5063x over previous
#include <cuda_runtime.h>
#include <cuda_bf16.h>
#include <cstdint>
#include <cstddef>

// Problem constants
#define T_STEPS 784
#define NBATCH  128
#define HID     512
#define OUTC    10
#define DECAY   0.2f
#define THRESH  0.5f
#define KDIM    512

// Two-chunk overlap
#define NCHK 2
#define TCH  392               // T_STEPS / NCHK
#define UNR  14                // 392 = 28 * 14
#define NBLKC (TCH / UNR)      // 28

// GEMM tiling
#define BM 128
#define BN 128
#define BK 64
#define ROWB 144u              // smem bytes per row: 64 bf16 (128B) + 16B pad
#define TILEB (128u * ROWB)    // 18432 B
#define STAGEB (3u * TILEB)    // A + Wh + Wl per stage
#define GEMM_SMEM (2u * STAGEB + 512u)  // + jrow[128] ints

#define SEQ_ELEMS ((size_t)T_STEPS * NBATCH * HID)
__device__ __nv_bfloat16 g_S1b[SEQ_ELEMS];   // layer-1 spikes [t][n][i] (exact 0/1)
__device__ __nv_bfloat16 g_S2b[SEQ_ELEMS];   // layer-2 spikes
__device__ float         g_C  [SEQ_ELEMS];   // GEMM output [t][n][j] fp32 (dense)
__device__ __nv_bfloat16 g_W2h[HID*HID], g_W2l[HID*HID];
__device__ __nv_bfloat16 g_W3h[HID*HID], g_W3l[HID*HID];
__device__ float         g_maskT[3][T_STEPS * HID];   // transposed masks [T][H]
// N-compaction metadata (l=0: mask2, l=1: mask3)
__device__ int g_jl [2][T_STEPS * HID];
__device__ int g_cnt[2][T_STEPS];
// Chunk-carried recurrence state per layer
__device__ float g_mem[3][NBATCH*HID];
__device__ float g_spk[3][NBATCH*HID];
__device__ float g_ss [3][NBATCH*HID];

// ---------------------------------------------------------------------------
// PTX helpers
// ---------------------------------------------------------------------------
__device__ __forceinline__ uint32_t smem_u32(const void* p){
    uint32_t a;
    asm("{ .reg .u64 t; cvta.to.shared.u64 t, %1; cvt.u32.u64 %0, t; }" : "=r"(a) : "l"(p));
    return a;
}
__device__ __forceinline__ void cp16(uint32_t saddr, const void* gaddr){
    asm volatile("cp.async.cg.shared.global [%0], [%1], 16;" :: "r"(saddr), "l"(gaddr));
}
__device__ __forceinline__ void ldsm4(uint32_t* r, uint32_t addr){
    asm volatile("ldmatrix.sync.aligned.m8n8.x4.shared.b16 {%0,%1,%2,%3}, [%4];"
        : "=r"(r[0]), "=r"(r[1]), "=r"(r[2]), "=r"(r[3]) : "r"(addr));
}
__device__ __forceinline__ void mma_bf16(float* c, const uint32_t* a, const uint32_t* b){
    asm volatile(
        "mma.sync.aligned.m16n8k16.row.col.f32.bf16.bf16.f32 "
        "{%0,%1,%2,%3}, {%4,%5,%6,%7}, {%8,%9}, {%0,%1,%2,%3};"
        : "+f"(c[0]), "+f"(c[1]), "+f"(c[2]), "+f"(c[3])
        : "r"(a[0]), "r"(a[1]), "r"(a[2]), "r"(a[3]), "r"(b[0]), "r"(b[1]));
}

// ---------------------------------------------------------------------------
// Weight split
// ---------------------------------------------------------------------------
__global__ void split_kernel(const float* __restrict__ W2, const float* __restrict__ W3){
    int idx = blockIdx.x * blockDim.x + threadIdx.x;
    if (idx < HID * HID){
        float w = W2[idx];
        __nv_bfloat16 h = __float2bfloat16(w);
        g_W2h[idx] = h;
        g_W2l[idx] = __float2bfloat16(w - __bfloat162float(h));
        w = W3[idx];
        h = __float2bfloat16(w);
        g_W3h[idx] = h;
        g_W3l[idx] = __float2bfloat16(w - __bfloat162float(h));
    }
}

// ---------------------------------------------------------------------------
// Mask transpose [H][T] -> [T][H]
// ---------------------------------------------------------------------------
__global__ void maskT_kernel(const float* __restrict__ m1,
                             const float* __restrict__ m2,
                             const float* __restrict__ m3)
{
    __shared__ float tile[32][33];
    const float* src = (blockIdx.z == 0) ? m1 : (blockIdx.z == 1) ? m2 : m3;
    const int jb = blockIdx.x * 32;
    const int tb = blockIdx.y * 32;
    const int tx = threadIdx.x, ty = threadIdx.y;

    if (tb + tx < T_STEPS)
        tile[ty][tx] = src[(size_t)(jb + ty) * T_STEPS + tb + tx];
    __syncthreads();
    if (tb + ty < T_STEPS)
        g_maskT[blockIdx.z][(size_t)(tb + ty) * HID + jb + tx] = tile[tx][ty];
}

// ---------------------------------------------------------------------------
// Active-column compaction: per (t, mask) prefix-scan -> jlist + count.
// ---------------------------------------------------------------------------
__global__ void compact_kernel(const float* __restrict__ m2,
                               const float* __restrict__ m3)
{
    const int t = blockIdx.x;
    const int l = blockIdx.y;
    const float* __restrict__ src = l ? m3 : m2;
    const int j = threadIdx.x;
    __shared__ int scan[HID];

    const int on = (src[(size_t)j * T_STEPS + t] != 0.f) ? 1 : 0;
    int v = on;
    scan[j] = v;
    __syncthreads();
    #pragma unroll
    for (int o = 1; o < HID; o <<= 1){
        const int add = (j >= o) ? scan[j - o] : 0;
        __syncthreads();
        v += add;
        scan[j] = v;
        __syncthreads();
    }
    if (on) g_jl[l][t * HID + (v - 1)] = j;
    if (j == HID - 1) g_cnt[l][t] = v;
}

// ---------------------------------------------------------------------------
// Layer-1 recurrence chunk c: t in [c*TCH, (c+1)*TCH).
// ---------------------------------------------------------------------------
__global__ void layer1_kernel(const float* __restrict__ x,
                              const float* __restrict__ W1,
                              const float* __restrict__ b1,
                              float* __restrict__ fr1,
                              int c)
{
    const int n = blockIdx.x;
    const int i = blockIdx.y * 128 + threadIdx.x;
    const int sid = n * HID + i;
    const float w = W1[i];
    const float b = b1[i];
    const float* __restrict__ xr = x + (size_t)n * T_STEPS;
    const float* __restrict__ mk = g_maskT[0];
    __nv_bfloat16* __restrict__ sOut = g_S1b + (size_t)n * HID + i;
    const size_t cstr = (size_t)NBATCH * HID;
    const int t0 = c * TCH;

    float mem, spike, ss;
    if (c == 0){ mem = 0.f; spike = 0.f; ss = 0.f; }
    else { mem = g_mem[0][sid]; spike = g_spk[0][sid]; ss = g_ss[0][sid]; }

    float xb[2][UNR], mb[2][UNR];
    #pragma unroll
    for (int u = 0; u < UNR; ++u){
        xb[0][u] = xr[t0 + u];
        mb[0][u] = mk[(size_t)(t0 + u) * HID + i];
    }

    for (int tc = 0; tc < NBLKC; ++tc){
        const int cur = tc & 1, nxt = cur ^ 1;
        const int tb = t0 + tc * UNR;
        if (tc + 1 < NBLKC){
            #pragma unroll
            for (int u = 0; u < UNR; ++u){
                xb[nxt][u] = xr[tb + UNR + u];
                mb[nxt][u] = mk[(size_t)(tb + UNR + u) * HID + i];
            }
        }
        #pragma unroll
        for (int u = 0; u < UNR; ++u){
            const float m_t = mb[cur][u];
            const float new_mem = mem * DECAY * (1.f - spike) + xb[cur][u] * w + b;
            if (m_t != 0.f) mem = new_mem;
            const float spk = (mem > THRESH) ? m_t : 0.f;
            sOut[(size_t)(tb + u) * cstr] = __float2bfloat16(spk);
            ss += spk;
            spike = spk;
        }
    }
    if (c == NCHK - 1){
        fr1[sid] = ss * (1.f / (float)T_STEPS);
    } else {
        g_mem[0][sid] = mem; g_spk[0][sid] = spike; g_ss[0][sid] = ss;
    }
}

// ---------------------------------------------------------------------------
// bf16 HMMA GEMM, N-compacted compute, dense-C scatter. Chunk cbase:
// t = cbase*TCH + blockIdx.y.
// ---------------------------------------------------------------------------
__global__ void __launch_bounds__(256, 2)
gemm_bf16(int which, int cbase)
{
    extern __shared__ char smem[];
    const int t = cbase * TCH + blockIdx.y;
    const int cnt = g_cnt[which][t];
    const int n0 = blockIdx.x * BN;          // pos-space tile base
    if (n0 >= cnt) return;

    const __nv_bfloat16* __restrict__ A  = which ? g_S2b : g_S1b;
    const __nv_bfloat16* __restrict__ Bh = which ? g_W3h : g_W2h;
    const __nv_bfloat16* __restrict__ Bl = which ? g_W3l : g_W2l;
    const int* __restrict__ jl = g_jl[which] + t * HID + n0;

    const uint32_t sb = smem_u32(smem);
    int* jrow_s = (int*)(smem + 2u * STAGEB);
    const int tid  = threadIdx.x;
    const int lane = tid & 31;
    const int wrp  = tid >> 5;
    const int wm   = wrp & 1;
    const int wn   = wrp >> 1;
    const int m0 = t * BM;
    const int climit = cnt - n0;

    if (tid < 128) jrow_s[tid] = (tid < climit) ? jl[tid] : 0;
    __syncthreads();

    auto load_stage = [&](int st, int c){
        const uint32_t base = sb + (uint32_t)st * STAGEB;
        #pragma unroll
        for (int i = 0; i < 4; ++i){
            const int q   = tid + 256 * i;
            const int row = q >> 3;
            const int kc  = q & 7;
            const uint32_t soff = (uint32_t)row * ROWB + (uint32_t)kc * 16u;
            const size_t gk = (size_t)c * BK + (size_t)kc * 8;
            const int jr = jrow_s[row];
            cp16(base + soff,             A  + (size_t)(m0 + row) * KDIM + gk);
            cp16(base + TILEB + soff,     Bh + (size_t)jr * KDIM + gk);
            cp16(base + 2u*TILEB + soff,  Bl + (size_t)jr * KDIM + gk);
        }
        asm volatile("cp.async.commit_group;" ::: "memory");
    };

    float acc[4][4][4];
    #pragma unroll
    for (int mi = 0; mi < 4; ++mi)
        #pragma unroll
        for (int ni = 0; ni < 4; ++ni)
            #pragma unroll
            for (int q = 0; q < 4; ++q) acc[mi][ni][q] = 0.f;

    const uint32_t aOff = (uint32_t)(wm * 64 + (lane & 15)) * ROWB
                        + (uint32_t)((lane >> 4) << 3) * 2u;
    const uint32_t bOff = (uint32_t)(wn * 32 + ((lane >> 4) << 3) + (lane & 7)) * ROWB
                        + (uint32_t)(((lane >> 3) & 1) << 4);

    load_stage(0, 0);

    const int NC = KDIM / BK;   // 8
    for (int c = 0; c < NC; ++c){
        if (c + 1 < NC){
            load_stage((c + 1) & 1, c + 1);
            asm volatile("cp.async.wait_group 1;" ::: "memory");
        } else {
            asm volatile("cp.async.wait_group 0;" ::: "memory");
        }
        __syncthreads();

        const uint32_t base = sb + (uint32_t)(c & 1) * STAGEB;
        const uint32_t aB = base + aOff;
        const uint32_t hB = base + TILEB + bOff;
        const uint32_t lB = base + 2u*TILEB + bOff;

        #pragma unroll
        for (int k16 = 0; k16 < 4; ++k16){
            uint32_t a[4][4], bh[2][4], bl[2][4];
            #pragma unroll
            for (int mi = 0; mi < 4; ++mi)
                ldsm4(a[mi], aB + (uint32_t)(mi * 16) * ROWB + (uint32_t)k16 * 32u);
            #pragma unroll
            for (int p = 0; p < 2; ++p){
                ldsm4(bh[p], hB + (uint32_t)(p * 16) * ROWB + (uint32_t)k16 * 32u);
                ldsm4(bl[p], lB + (uint32_t)(p * 16) * ROWB + (uint32_t)k16 * 32u);
            }
            #pragma unroll
            for (int mi = 0; mi < 4; ++mi)
                #pragma unroll
                for (int ni = 0; ni < 4; ++ni){
                    mma_bf16(acc[mi][ni], a[mi], &bh[ni >> 1][(ni & 1) * 2]);
                    mma_bf16(acc[mi][ni], a[mi], &bl[ni >> 1][(ni & 1) * 2]);
                }
        }
        __syncthreads();
    }

    // Scatter epilogue: local pos -> dense column j = jrow_s[pos].
    const int rloc = wm * 64 + (lane >> 2);
    const int pbase = wn * 32 + (lane & 3) * 2;
    #pragma unroll
    for (int mi = 0; mi < 4; ++mi){
        float* row0 = g_C + (size_t)(m0 + rloc + mi * 16) * HID;
        float* row1 = row0 + 8 * HID;
        #pragma unroll
        for (int ni = 0; ni < 4; ++ni){
            const int pl = pbase + ni * 8;
            if (pl < climit){
                const int j0 = jrow_s[pl];
                row0[j0] = acc[mi][ni][0];
                row1[j0] = acc[mi][ni][2];
            }
            if (pl + 1 < climit){
                const int j1 = jrow_s[pl + 1];
                row0[j1] = acc[mi][ni][1];
                row1[j1] = acc[mi][ni][3];
            }
        }
    }
}

// ---------------------------------------------------------------------------
// Layer-2/3 recurrence chunk (dense C read; mask gate discards dead columns).
// layer==2 stores spikes. State carried in g_mem/g_spk/g_ss[layer-1].
// ---------------------------------------------------------------------------
__global__ void layerR_kernel(const float* __restrict__ bvec,
                              float* __restrict__ fr,
                              int maskSel, int layer, int c)
{
    const int n = blockIdx.x;
    const int j = blockIdx.y * 128 + threadIdx.x;
    const int sid = n * HID + j;
    const int L = layer - 1;
    const float bj = bvec[j];
    const float* __restrict__ mk = g_maskT[maskSel];
    const size_t cstr = (size_t)NBATCH * HID;
    const float* __restrict__ cPtr = g_C + (size_t)n * HID + j;
    __nv_bfloat16* __restrict__ sOut = g_S2b + (size_t)n * HID + j;
    const int t0 = c * TCH;

    float mem, spike, ss;
    if (c == 0){ mem = 0.f; spike = 0.f; ss = 0.f; }
    else { mem = g_mem[L][sid]; spike = g_spk[L][sid]; ss = g_ss[L][sid]; }

    float cb[2][UNR], mb[2][UNR];
    #pragma unroll
    for (int u = 0; u < UNR; ++u){
        cb[0][u] = cPtr[(size_t)(t0 + u) * cstr];
        mb[0][u] = mk[(size_t)(t0 + u) * HID + j];
    }

    for (int tc = 0; tc < NBLKC; ++tc){
        const int cur = tc & 1, nxt = cur ^ 1;
        const int tb = t0 + tc * UNR;
        if (tc + 1 < NBLKC){
            #pragma unroll
            for (int u = 0; u < UNR; ++u){
                cb[nxt][u] = cPtr[(size_t)(tb + UNR + u) * cstr];
                mb[nxt][u] = mk[(size_t)(tb + UNR + u) * HID + j];
            }
        }
        #pragma unroll
        for (int u = 0; u < UNR; ++u){
            const float m_t = mb[cur][u];
            const float new_mem = mem * DECAY * (1.f - spike) + cb[cur][u] + bj;
            if (m_t != 0.f) mem = new_mem;
            const float spk = (mem > THRESH) ? m_t : 0.f;
            if (layer == 2) sOut[(size_t)(tb + u) * cstr] = __float2bfloat16(spk);
            ss += spk;
            spike = spk;
        }
    }
    if (c == NCHK - 1){
        fr[sid] = ss * (1.f / (float)T_STEPS);
    } else {
        g_mem[L][sid] = mem; g_spk[L][sid] = spike; g_ss[L][sid] = ss;
    }
}

// ---------------------------------------------------------------------------
// Head: outputs[n][oc] = fr3[n] . W4[oc] + b4[oc]
// ---------------------------------------------------------------------------
__global__ void head_kernel(const float* __restrict__ fr3,
                            const float* __restrict__ W4,
                            const float* __restrict__ b4,
                            float* __restrict__ outputs)
{
    const int n = blockIdx.x;
    const int warp = threadIdx.x >> 5;
    const int lane = threadIdx.x & 31;
    const float* __restrict__ f = fr3 + (size_t)n * HID;
    const float* __restrict__ w = W4 + (size_t)warp * HID;
    float s = 0.f;
    for (int j = lane; j < HID; j += 32) s += f[j] * w[j];
#pragma unroll
    for (int o = 16; o > 0; o >>= 1) s += __shfl_xor_sync(0xffffffffu, s, o);
    if (lane == 0) outputs[n * OUTC + warp] = s + b4[warp];
}

// ---------------------------------------------------------------------------
// layer_fr[l] = mean(fr_l)
// ---------------------------------------------------------------------------
__global__ void lfr_kernel(const float* __restrict__ fr_all,
                           float* __restrict__ out3)
{
    const int l = blockIdx.x;
    const float* __restrict__ f = fr_all + (size_t)l * (NBATCH * HID);
    __shared__ float sh[256];
    float s = 0.f;
    for (int idx = threadIdx.x; idx < NBATCH * HID; idx += 256) s += f[idx];
    sh[threadIdx.x] = s;
    __syncthreads();
    for (int o = 128; o > 0; o >>= 1) {
        if (threadIdx.x < o) sh[threadIdx.x] += sh[threadIdx.x + o];
        __syncthreads();
    }
    if (threadIdx.x == 0) out3[l] = sh[0] * (1.f / (float)(NBATCH * HID));
}

// ---------------------------------------------------------------------------
// Launch: 2-chunk two-stream overlap. Stream 0 = GEMMs, sB = recurrences.
// ---------------------------------------------------------------------------
extern "C" void kernel_launch(void* const* d_in, const int* in_sizes, int n_in,
                              void* d_out, int out_size)
{
    const float* x     = (const float*)d_in[0];
    const float* W1    = (const float*)d_in[1];
    const float* b1    = (const float*)d_in[2];
    const float* W2    = (const float*)d_in[3];
    const float* b2    = (const float*)d_in[4];
    const float* W3    = (const float*)d_in[5];
    const float* b3    = (const float*)d_in[6];
    const float* W4    = (const float*)d_in[7];
    const float* b4    = (const float*)d_in[8];
    const float* mask1 = (const float*)d_in[9];
    const float* mask2 = (const float*)d_in[10];
    const float* mask3 = (const float*)d_in[11];

    float* out     = (float*)d_out;
    float* outputs = out;
    float* fr1     = out + NBATCH * OUTC;
    float* fr2     = fr1 + NBATCH * HID;
    float* fr3     = fr2 + NBATCH * HID;
    float* lfr     = fr3 + NBATCH * HID;

    static cudaStream_t sB = nullptr;
    static cudaEvent_t evF, evJ;
    static cudaEvent_t eL1[NCHK], eG1[NCHK], eL2[NCHK], eG2[NCHK];
    if (!sB){
        cudaStreamCreateWithFlags(&sB, cudaStreamNonBlocking);
        cudaEventCreateWithFlags(&evF, cudaEventDisableTiming);
        cudaEventCreateWithFlags(&evJ, cudaEventDisableTiming);
        for (int c = 0; c < NCHK; ++c){
            cudaEventCreateWithFlags(&eL1[c], cudaEventDisableTiming);
            cudaEventCreateWithFlags(&eG1[c], cudaEventDisableTiming);
            cudaEventCreateWithFlags(&eL2[c], cudaEventDisableTiming);
            cudaEventCreateWithFlags(&eG2[c], cudaEventDisableTiming);
        }
        cudaFuncSetAttribute(gemm_bf16, cudaFuncAttributeMaxDynamicSharedMemorySize, GEMM_SMEM);
    }

    dim3 gemm_grid(4, TCH);           // per-chunk: 4 pos-tiles x 392 t
    dim3 rec_grid(NBATCH, HID / 128);
    dim3 mt_grid(HID / 32, (T_STEPS + 31) / 32, 3);

    // Fork
    cudaEventRecord(evF, 0);
    cudaStreamWaitEvent(sB, evF, 0);

    // Stream 0: weight split + compaction (GEMM prerequisites)
    split_kernel<<<(HID*HID + 255)/256, 256>>>(W2, W3);
    compact_kernel<<<dim3(T_STEPS, 2), HID>>>(mask2, mask3);

    // Stream B: mask transpose, then L1 chunks
    maskT_kernel<<<mt_grid, dim3(32, 32), 0, sB>>>(mask1, mask2, mask3);
    for (int c = 0; c < NCHK; ++c){
        layer1_kernel<<<rec_grid, 128, 0, sB>>>(x, W1, b1, fr1, c);
        cudaEventRecord(eL1[c], sB);
    }

    // Stream 0: G1 chunks
    for (int c = 0; c < NCHK; ++c){
        cudaStreamWaitEvent(0, eL1[c], 0);
        gemm_bf16<<<gemm_grid, 256, GEMM_SMEM>>>(0, c);
        cudaEventRecord(eG1[c], 0);
    }
    // Stream B: L2 chunks
    for (int c = 0; c < NCHK; ++c){
        cudaStreamWaitEvent(sB, eG1[c], 0);
        layerR_kernel<<<rec_grid, 128, 0, sB>>>(b2, fr2, 1, 2, c);
        cudaEventRecord(eL2[c], sB);
    }
    // Stream 0: G2 chunks
    for (int c = 0; c < NCHK; ++c){
        cudaStreamWaitEvent(0, eL2[c], 0);
        gemm_bf16<<<gemm_grid, 256, GEMM_SMEM>>>(1, c);
        cudaEventRecord(eG2[c], 0);
    }
    // Stream B: L3 chunks
    for (int c = 0; c < NCHK; ++c){
        cudaStreamWaitEvent(sB, eG2[c], 0);
        layerR_kernel<<<rec_grid, 128, 0, sB>>>(b3, fr3, 2, 3, c);
    }

    // Join; finish on stream 0
    cudaEventRecord(evJ, sB);
    cudaStreamWaitEvent(0, evJ, 0);
    head_kernel<<<NBATCH, 320>>>(fr3, W4, b4, outputs);
    lfr_kernel<<<3, 256>>>(fr1, lfr);
}

// round 10
// speedup vs baseline: 1.7018x; 1.1298x over previous
#include <cuda_runtime.h>
#include <cuda_bf16.h>
#include <cstdint>
#include <cstddef>

// Problem constants
#define T_STEPS 784
#define NBATCH  128
#define HID     512
#define OUTC    10
#define DECAY   0.2f
#define THRESH  0.5f
#define KDIM    512

// GEMM tiling
#define BM 128
#define BN 128
#define BK 64
#define ROWB 144u              // smem bytes per row: 64 bf16 (128B) + 16B pad
#define TILEB (128u * ROWB)    // 18432 B
#define STAGEB (3u * TILEB)    // A + Wh + Wl per stage
#define GEMM_SMEM (2u * STAGEB)

// Recurrence pipelining
#define UNR 16                 // 784 = 49 * 16
#define NBLK (T_STEPS / UNR)   // 49

// Packed spikes: 512 bits per (t,n) row = 16 words = 64 bytes
#define WPR 16
#define SEQ_ELEMS ((size_t)T_STEPS * NBATCH * HID)
__device__ uint32_t g_S1p[(size_t)T_STEPS * NBATCH * WPR];
__device__ uint32_t g_S2p[(size_t)T_STEPS * NBATCH * WPR];
__device__ float    g_C  [SEQ_ELEMS];        // GEMM output [t][n][j] fp32 dense
__device__ __nv_bfloat16 g_W2h[HID*HID], g_W2l[HID*HID];
__device__ __nv_bfloat16 g_W3h[HID*HID], g_W3l[HID*HID];
__device__ float    g_maskT[3][T_STEPS * HID];   // transposed masks [T][H]

// ---------------------------------------------------------------------------
// PTX helpers
// ---------------------------------------------------------------------------
__device__ __forceinline__ uint32_t smem_u32(const void* p){
    uint32_t a;
    asm("{ .reg .u64 t; cvta.to.shared.u64 t, %1; cvt.u32.u64 %0, t; }" : "=r"(a) : "l"(p));
    return a;
}
__device__ __forceinline__ void cp16(uint32_t saddr, const void* gaddr){
    asm volatile("cp.async.cg.shared.global [%0], [%1], 16;" :: "r"(saddr), "l"(gaddr));
}
__device__ __forceinline__ void ldsm4(uint32_t* r, uint32_t addr){
    asm volatile("ldmatrix.sync.aligned.m8n8.x4.shared.b16 {%0,%1,%2,%3}, [%4];"
        : "=r"(r[0]), "=r"(r[1]), "=r"(r[2]), "=r"(r[3]) : "r"(addr));
}
__device__ __forceinline__ void mma_bf16(float* c, const uint32_t* a, const uint32_t* b){
    asm volatile(
        "mma.sync.aligned.m16n8k16.row.col.f32.bf16.bf16.f32 "
        "{%0,%1,%2,%3}, {%4,%5,%6,%7}, {%8,%9}, {%0,%1,%2,%3};"
        : "+f"(c[0]), "+f"(c[1]), "+f"(c[2]), "+f"(c[3])
        : "r"(a[0]), "r"(a[1]), "r"(a[2]), "r"(a[3]), "r"(b[0]), "r"(b[1]));
}

// ---------------------------------------------------------------------------
// Weight split: W -> hi(bf16) + lo(bf16)
// ---------------------------------------------------------------------------
__global__ void split_kernel(const float* __restrict__ W2, const float* __restrict__ W3){
    int idx = blockIdx.x * blockDim.x + threadIdx.x;
    if (idx < HID * HID){
        float w = W2[idx];
        __nv_bfloat16 h = __float2bfloat16(w);
        g_W2h[idx] = h;
        g_W2l[idx] = __float2bfloat16(w - __bfloat162float(h));
        w = W3[idx];
        h = __float2bfloat16(w);
        g_W3h[idx] = h;
        g_W3l[idx] = __float2bfloat16(w - __bfloat162float(h));
    }
}

// ---------------------------------------------------------------------------
// Mask transpose: [H][T] -> [T][H]
// ---------------------------------------------------------------------------
__global__ void maskT_kernel(const float* __restrict__ m1,
                             const float* __restrict__ m2,
                             const float* __restrict__ m3)
{
    __shared__ float tile[32][33];
    const float* src = (blockIdx.z == 0) ? m1 : (blockIdx.z == 1) ? m2 : m3;
    const int jb = blockIdx.x * 32;
    const int tb = blockIdx.y * 32;
    const int tx = threadIdx.x, ty = threadIdx.y;

    if (tb + tx < T_STEPS)
        tile[ty][tx] = src[(size_t)(jb + ty) * T_STEPS + tb + tx];
    __syncthreads();
    if (tb + ty < T_STEPS)
        g_maskT[blockIdx.z][(size_t)(tb + ty) * HID + jb + tx] = tile[tx][ty];
}

// ---------------------------------------------------------------------------
// Layer-1 recurrence, 16-step register double-buffer. Spikes packed 1-bit
// via ballot: warp lane l owns neuron i0+l; lane0 stores the 32-bit word.
// ---------------------------------------------------------------------------
__global__ void layer1_kernel(const float* __restrict__ x,
                              const float* __restrict__ W1,
                              const float* __restrict__ b1,
                              float* __restrict__ fr1)
{
    const int n = blockIdx.x;
    const int i = blockIdx.y * 128 + threadIdx.x;
    const int lane = threadIdx.x & 31;
    const float w = W1[i];
    const float b = b1[i];
    const float* __restrict__ xr = x + (size_t)n * T_STEPS;
    const float* __restrict__ mk = g_maskT[0];
    uint32_t* __restrict__ pOut = g_S1p + (size_t)n * WPR
                                + (blockIdx.y * 4) + (threadIdx.x >> 5);
    const size_t pstr = (size_t)NBATCH * WPR;   // words per timestep

    float xb[2][UNR], mb[2][UNR];
    #pragma unroll
    for (int u = 0; u < UNR; ++u){
        xb[0][u] = xr[u];
        mb[0][u] = mk[(size_t)u * HID + i];
    }

    float mem = 0.f, spike = 0.f, ss = 0.f;
    for (int tc = 0; tc < NBLK; ++tc){
        const int cur = tc & 1, nxt = cur ^ 1;
        const int tb = tc * UNR;
        if (tc + 1 < NBLK){
            #pragma unroll
            for (int u = 0; u < UNR; ++u){
                xb[nxt][u] = xr[tb + UNR + u];
                mb[nxt][u] = mk[(size_t)(tb + UNR + u) * HID + i];
            }
        }
        #pragma unroll
        for (int u = 0; u < UNR; ++u){
            const float m_t = mb[cur][u];
            const float new_mem = mem * DECAY * (1.f - spike) + xb[cur][u] * w + b;
            if (m_t != 0.f) mem = new_mem;
            const float spk = (mem > THRESH) ? m_t : 0.f;   // m_t is exactly 1.0 when on
            const unsigned bal = __ballot_sync(0xffffffffu, spk != 0.f);
            if (lane == 0) pOut[(size_t)(tb + u) * pstr] = bal;
            ss += spk;
            spike = spk;
        }
    }
    fr1[n * HID + i] = ss * (1.f / (float)T_STEPS);
}

// ---------------------------------------------------------------------------
// bf16 HMMA GEMM: C[m][j] = sum_k A[m][k]*(Wh[j][k]+Wl[j][k]), fp32 accum.
// A comes from 1-bit packed spikes, expanded to bf16 in smem (bit-identical
// to the old cp.async bytes: 1.0 = 0x3F80). B hi/lo via cp.async.
// ---------------------------------------------------------------------------
__global__ void __launch_bounds__(256, 2)
gemm_bf16(int which)
{
    extern __shared__ char smem[];
    const uint8_t* __restrict__ Ap = (const uint8_t*)(which ? g_S2p : g_S1p);
    const __nv_bfloat16* __restrict__ Bh = which ? g_W3h : g_W2h;
    const __nv_bfloat16* __restrict__ Bl = which ? g_W3l : g_W2l;

    const uint32_t sb = smem_u32(smem);
    const int tid  = threadIdx.x;
    const int lane = tid & 31;
    const int wrp  = tid >> 5;
    const int wm   = wrp & 1;          // 2 warp-rows of 64
    const int wn   = wrp >> 1;         // 4 warp-cols of 32
    const int n0 = blockIdx.x * BN;    // x = bn (4)  -> A reuse in L2
    const int m0 = blockIdx.y * BM;    // y = bm (784)

    auto load_stage = [&](int st, int c){
        const uint32_t base = sb + (uint32_t)st * STAGEB;
        char* abase = smem + (size_t)st * STAGEB;
        #pragma unroll
        for (int i = 0; i < 4; ++i){
            const int q   = tid + 256 * i;
            const int row = q >> 3;
            const int kc  = q & 7;
            const uint32_t soff = (uint32_t)row * ROWB + (uint32_t)kc * 16u;
            const size_t gk = (size_t)c * BK + (size_t)kc * 8;
            // A: 1 byte = 8 spikes -> 8 bf16 (4 packed uint32), STS.128
            const uint8_t bits = __ldg(Ap + (size_t)(m0 + row) * 64 + (size_t)c * 8 + kc);
            uint4 v;
            v.x = ((bits &   1u) ? 0x3F80u : 0u) | ((bits &   2u) ? 0x3F800000u : 0u);
            v.y = ((bits &   4u) ? 0x3F80u : 0u) | ((bits &   8u) ? 0x3F800000u : 0u);
            v.z = ((bits &  16u) ? 0x3F80u : 0u) | ((bits &  32u) ? 0x3F800000u : 0u);
            v.w = ((bits &  64u) ? 0x3F80u : 0u) | ((bits & 128u) ? 0x3F800000u : 0u);
            *(uint4*)(abase + soff) = v;
            // B hi/lo via cp.async
            cp16(base + TILEB + soff,     Bh + (size_t)(n0 + row) * KDIM + gk);
            cp16(base + 2u*TILEB + soff,  Bl + (size_t)(n0 + row) * KDIM + gk);
        }
        asm volatile("cp.async.commit_group;" ::: "memory");
    };

    float acc[4][4][4];
    #pragma unroll
    for (int mi = 0; mi < 4; ++mi)
        #pragma unroll
        for (int ni = 0; ni < 4; ++ni)
            #pragma unroll
            for (int q = 0; q < 4; ++q) acc[mi][ni][q] = 0.f;

    const uint32_t aOff = (uint32_t)(wm * 64 + (lane & 15)) * ROWB
                        + (uint32_t)((lane >> 4) << 3) * 2u;
    const uint32_t bOff = (uint32_t)(wn * 32 + ((lane >> 4) << 3) + (lane & 7)) * ROWB
                        + (uint32_t)(((lane >> 3) & 1) << 4);

    load_stage(0, 0);

    const int NC = KDIM / BK;   // 8
    for (int c = 0; c < NC; ++c){
        if (c + 1 < NC){
            load_stage((c + 1) & 1, c + 1);
            asm volatile("cp.async.wait_group 1;" ::: "memory");
        } else {
            asm volatile("cp.async.wait_group 0;" ::: "memory");
        }
        __syncthreads();

        const uint32_t base = sb + (uint32_t)(c & 1) * STAGEB;
        const uint32_t aB = base + aOff;
        const uint32_t hB = base + TILEB + bOff;
        const uint32_t lB = base + 2u*TILEB + bOff;

        #pragma unroll
        for (int k16 = 0; k16 < 4; ++k16){
            uint32_t a[4][4], bh[2][4], bl[2][4];
            #pragma unroll
            for (int mi = 0; mi < 4; ++mi)
                ldsm4(a[mi], aB + (uint32_t)(mi * 16) * ROWB + (uint32_t)k16 * 32u);
            #pragma unroll
            for (int p = 0; p < 2; ++p){
                ldsm4(bh[p], hB + (uint32_t)(p * 16) * ROWB + (uint32_t)k16 * 32u);
                ldsm4(bl[p], lB + (uint32_t)(p * 16) * ROWB + (uint32_t)k16 * 32u);
            }
            #pragma unroll
            for (int mi = 0; mi < 4; ++mi)
                #pragma unroll
                for (int ni = 0; ni < 4; ++ni){
                    mma_bf16(acc[mi][ni], a[mi], &bh[ni >> 1][(ni & 1) * 2]);
                    mma_bf16(acc[mi][ni], a[mi], &bl[ni >> 1][(ni & 1) * 2]);
                }
        }
        __syncthreads();
    }

    const int rbase = m0 + wm * 64 + (lane >> 2);
    const int cbase = n0 + wn * 32 + (lane & 3) * 2;
    #pragma unroll
    for (int mi = 0; mi < 4; ++mi){
        #pragma unroll
        for (int ni = 0; ni < 4; ++ni){
            float* p0 = g_C + (size_t)(rbase + mi * 16) * HID + cbase + ni * 8;
            float* p1 = p0 + 8 * HID;
            *(float2*)p0 = make_float2(acc[mi][ni][0], acc[mi][ni][1]);
            *(float2*)p1 = make_float2(acc[mi][ni][2], acc[mi][ni][3]);
        }
    }
}

// ---------------------------------------------------------------------------
// Layer-2/3 recurrence, 16-step register double-buffer. layer==2 writes
// packed spikes (ballot).
// ---------------------------------------------------------------------------
__global__ void layerR_kernel(const float* __restrict__ bvec,
                              float* __restrict__ fr,
                              int maskSel, int layer)
{
    const int n = blockIdx.x;
    const int j = blockIdx.y * 128 + threadIdx.x;
    const int lane = threadIdx.x & 31;
    const float bj = bvec[j];
    const float* __restrict__ mk = g_maskT[maskSel];
    const size_t cstr = (size_t)NBATCH * HID;
    const float* __restrict__ cPtr = g_C + (size_t)n * HID + j;
    uint32_t* __restrict__ pOut = g_S2p + (size_t)n * WPR
                                + (blockIdx.y * 4) + (threadIdx.x >> 5);
    const size_t pstr = (size_t)NBATCH * WPR;

    float cb[2][UNR], mb[2][UNR];
    #pragma unroll
    for (int u = 0; u < UNR; ++u){
        cb[0][u] = cPtr[(size_t)u * cstr];
        mb[0][u] = mk[(size_t)u * HID + j];
    }

    float mem = 0.f, spike = 0.f, ss = 0.f;
    for (int tc = 0; tc < NBLK; ++tc){
        const int cur = tc & 1, nxt = cur ^ 1;
        const int tb = tc * UNR;
        if (tc + 1 < NBLK){
            #pragma unroll
            for (int u = 0; u < UNR; ++u){
                cb[nxt][u] = cPtr[(size_t)(tb + UNR + u) * cstr];
                mb[nxt][u] = mk[(size_t)(tb + UNR + u) * HID + j];
            }
        }
        #pragma unroll
        for (int u = 0; u < UNR; ++u){
            const float m_t = mb[cur][u];
            const float new_mem = mem * DECAY * (1.f - spike) + cb[cur][u] + bj;
            if (m_t != 0.f) mem = new_mem;
            const float spk = (mem > THRESH) ? m_t : 0.f;
            if (layer == 2){
                const unsigned bal = __ballot_sync(0xffffffffu, spk != 0.f);
                if (lane == 0) pOut[(size_t)(tb + u) * pstr] = bal;
            }
            ss += spk;
            spike = spk;
        }
    }
    fr[n * HID + j] = ss * (1.f / (float)T_STEPS);
}

// ---------------------------------------------------------------------------
// Head: outputs[n][oc] = fr3[n] . W4[oc] + b4[oc]
// ---------------------------------------------------------------------------
__global__ void head_kernel(const float* __restrict__ fr3,
                            const float* __restrict__ W4,
                            const float* __restrict__ b4,
                            float* __restrict__ outputs)
{
    const int n = blockIdx.x;
    const int warp = threadIdx.x >> 5;
    const int lane = threadIdx.x & 31;
    const float* __restrict__ f = fr3 + (size_t)n * HID;
    const float* __restrict__ w = W4 + (size_t)warp * HID;
    float s = 0.f;
    for (int j = lane; j < HID; j += 32) s += f[j] * w[j];
#pragma unroll
    for (int o = 16; o > 0; o >>= 1) s += __shfl_xor_sync(0xffffffffu, s, o);
    if (lane == 0) outputs[n * OUTC + warp] = s + b4[warp];
}

// ---------------------------------------------------------------------------
// layer_fr[l] = mean(fr_l)
// ---------------------------------------------------------------------------
__global__ void lfr_kernel(const float* __restrict__ fr_all,
                           float* __restrict__ out3)
{
    const int l = blockIdx.x;
    const float* __restrict__ f = fr_all + (size_t)l * (NBATCH * HID);
    __shared__ float sh[256];
    float s = 0.f;
    for (int idx = threadIdx.x; idx < NBATCH * HID; idx += 256) s += f[idx];
    sh[threadIdx.x] = s;
    __syncthreads();
    for (int o = 128; o > 0; o >>= 1) {
        if (threadIdx.x < o) sh[threadIdx.x] += sh[threadIdx.x + o];
        __syncthreads();
    }
    if (threadIdx.x == 0) out3[l] = sh[0] * (1.f / (float)(NBATCH * HID));
}

// ---------------------------------------------------------------------------
// Launch (serial — proven fastest schedule)
// ---------------------------------------------------------------------------
extern "C" void kernel_launch(void* const* d_in, const int* in_sizes, int n_in,
                              void* d_out, int out_size)
{
    const float* x     = (const float*)d_in[0];
    const float* W1    = (const float*)d_in[1];
    const float* b1    = (const float*)d_in[2];
    const float* W2    = (const float*)d_in[3];
    const float* b2    = (const float*)d_in[4];
    const float* W3    = (const float*)d_in[5];
    const float* b3    = (const float*)d_in[6];
    const float* W4    = (const float*)d_in[7];
    const float* b4    = (const float*)d_in[8];
    const float* mask1 = (const float*)d_in[9];
    const float* mask2 = (const float*)d_in[10];
    const float* mask3 = (const float*)d_in[11];

    float* out     = (float*)d_out;
    float* outputs = out;
    float* fr1     = out + NBATCH * OUTC;
    float* fr2     = fr1 + NBATCH * HID;
    float* fr3     = fr2 + NBATCH * HID;
    float* lfr     = fr3 + NBATCH * HID;

    cudaFuncSetAttribute(gemm_bf16, cudaFuncAttributeMaxDynamicSharedMemorySize, GEMM_SMEM);

    dim3 gemm_grid(4, T_STEPS);       // x = bn, y = bm
    dim3 rec_grid(NBATCH, HID / 128); // 512 CTAs, 128 threads
    dim3 mt_grid(HID / 32, (T_STEPS + 31) / 32, 3);

    maskT_kernel<<<mt_grid, dim3(32, 32)>>>(mask1, mask2, mask3);
    split_kernel<<<(HID*HID + 255)/256, 256>>>(W2, W3);
    layer1_kernel<<<rec_grid, 128>>>(x, W1, b1, fr1);
    gemm_bf16<<<gemm_grid, 256, GEMM_SMEM>>>(0);
    layerR_kernel<<<rec_grid, 128>>>(b2, fr2, 1, 2);
    gemm_bf16<<<gemm_grid, 256, GEMM_SMEM>>>(1);
    layerR_kernel<<<rec_grid, 128>>>(b3, fr3, 2, 3);
    head_kernel<<<NBATCH, 320>>>(fr3, W4, b4, outputs);
    lfr_kernel<<<3, 256>>>(fr1, lfr);
}

// round 11
// speedup vs baseline: 1.8702x; 1.0990x over previous
#include <cuda_runtime.h>
#include <cuda_bf16.h>
#include <cstdint>
#include <cstddef>

// Problem constants
#define T_STEPS 784
#define NBATCH  128
#define HID     512
#define OUTC    10
#define DECAY   0.2f
#define THRESH  0.5f
#define KDIM    512

// GEMM tiling
#define BM 128
#define BN 128
#define BK 64
#define ROWB 144u              // smem bytes per row: 64 bf16 (128B) + 16B pad
#define TILEB (128u * ROWB)    // 18432 B
#define STAGEB (3u * TILEB)    // A + Bh + Bl per stage
#define GEMM_SMEM (2u * STAGEB)

// Recurrence pipelining
#define UNR 16                 // 784 = 49 * 16
#define NBLK (T_STEPS / UNR)   // 49
#define NWORDS 25              // ceil(784/32)

// Packed spikes: 512 bits per (t,n) row = 16 words = 64 bytes
#define WPR 16
#define SEQ_ELEMS ((size_t)T_STEPS * NBATCH * HID)
__device__ uint32_t g_S1p[(size_t)T_STEPS * NBATCH * WPR];
__device__ uint32_t g_S2p[(size_t)T_STEPS * NBATCH * WPR];
__device__ float    g_C  [SEQ_ELEMS];        // GEMM output [t][n][j] fp32 dense
__device__ __nv_bfloat16 g_W2h[HID*HID], g_W2l[HID*HID];
__device__ __nv_bfloat16 g_W3h[HID*HID], g_W3l[HID*HID];
__device__ uint32_t g_mkb[3][NWORDS * HID];  // bit-packed masks: word w, neuron j

// ---------------------------------------------------------------------------
// PTX helpers
// ---------------------------------------------------------------------------
__device__ __forceinline__ uint32_t smem_u32(const void* p){
    uint32_t a;
    asm("{ .reg .u64 t; cvta.to.shared.u64 t, %1; cvt.u32.u64 %0, t; }" : "=r"(a) : "l"(p));
    return a;
}
__device__ __forceinline__ void cp16(uint32_t saddr, const void* gaddr){
    asm volatile("cp.async.cg.shared.global [%0], [%1], 16;" :: "r"(saddr), "l"(gaddr));
}
__device__ __forceinline__ void ldsm4(uint32_t* r, uint32_t addr){
    asm volatile("ldmatrix.sync.aligned.m8n8.x4.shared.b16 {%0,%1,%2,%3}, [%4];"
        : "=r"(r[0]), "=r"(r[1]), "=r"(r[2]), "=r"(r[3]) : "r"(addr));
}
__device__ __forceinline__ void mma_bf16(float* c, const uint32_t* a, const uint32_t* b){
    asm volatile(
        "mma.sync.aligned.m16n8k16.row.col.f32.bf16.bf16.f32 "
        "{%0,%1,%2,%3}, {%4,%5,%6,%7}, {%8,%9}, {%0,%1,%2,%3};"
        : "+f"(c[0]), "+f"(c[1]), "+f"(c[2]), "+f"(c[3])
        : "r"(a[0]), "r"(a[1]), "r"(a[2]), "r"(a[3]), "r"(b[0]), "r"(b[1]));
}

// ---------------------------------------------------------------------------
// Weight split: W -> hi(bf16) + lo(bf16)
// ---------------------------------------------------------------------------
__global__ void split_kernel(const float* __restrict__ W2, const float* __restrict__ W3){
    int idx = blockIdx.x * blockDim.x + threadIdx.x;
    if (idx < HID * HID){
        float w = W2[idx];
        __nv_bfloat16 h = __float2bfloat16(w);
        g_W2h[idx] = h;
        g_W2l[idx] = __float2bfloat16(w - __bfloat162float(h));
        w = W3[idx];
        h = __float2bfloat16(w);
        g_W3h[idx] = h;
        g_W3l[idx] = __float2bfloat16(w - __bfloat162float(h));
    }
}

// ---------------------------------------------------------------------------
// Mask bit-pack: [H][T] floats -> [NWORDS][H] words (bit b = t=32w+b on).
// grid (NWORDS, 3), block HID.
// ---------------------------------------------------------------------------
__global__ void maskbits_kernel(const float* __restrict__ m1,
                                const float* __restrict__ m2,
                                const float* __restrict__ m3)
{
    const int w = blockIdx.x;
    const int l = blockIdx.y;
    const int j = threadIdx.x;
    const float* __restrict__ src = (l == 0) ? m1 : (l == 1) ? m2 : m3;
    uint32_t bits = 0;
    #pragma unroll
    for (int b = 0; b < 32; ++b){
        const int t = w * 32 + b;
        if (t < T_STEPS && src[(size_t)j * T_STEPS + t] != 0.f) bits |= (1u << b);
    }
    g_mkb[l][w * HID + j] = bits;
}

// ---------------------------------------------------------------------------
// Layer-1 recurrence: bit-mask gating, 16-step register double-buffer for x,
// ballot-packed spike output.
// ---------------------------------------------------------------------------
__global__ void layer1_kernel(const float* __restrict__ x,
                              const float* __restrict__ W1,
                              const float* __restrict__ b1,
                              float* __restrict__ fr1)
{
    const int n = blockIdx.x;
    const int i = blockIdx.y * 128 + threadIdx.x;
    const int lane = threadIdx.x & 31;
    const float w = W1[i];
    const float b = b1[i];
    const float* __restrict__ xr = x + (size_t)n * T_STEPS;
    const uint32_t* __restrict__ mkb = g_mkb[0];
    uint32_t* __restrict__ pOut = g_S1p + (size_t)n * WPR
                                + (blockIdx.y * 4) + (threadIdx.x >> 5);
    const size_t pstr = (size_t)NBATCH * WPR;

    uint32_t mcur = mkb[i];
    uint32_t mnxt = mkb[HID + i];

    float xb[2][UNR];
    #pragma unroll
    for (int u = 0; u < UNR; ++u) xb[0][u] = xr[u];

    float mem = 0.f, spike = 0.f, ss = 0.f;
    for (int tc = 0; tc < NBLK; ++tc){
        const int cur = tc & 1, nxt = cur ^ 1;
        const int tb = tc * UNR;
        if (tc + 1 < NBLK){
            #pragma unroll
            for (int u = 0; u < UNR; ++u) xb[nxt][u] = xr[tb + UNR + u];
        }
        const uint32_t bits16 = (tc & 1) ? (mcur >> 16) : mcur;
        #pragma unroll
        for (int u = 0; u < UNR; ++u){
            const bool on = (bits16 >> u) & 1u;
            const float new_mem = mem * DECAY * (1.f - spike) + xb[cur][u] * w + b;
            if (on) mem = new_mem;
            const float spk = (mem > THRESH && on) ? 1.f : 0.f;
            const unsigned bal = __ballot_sync(0xffffffffu, spk != 0.f);
            if (lane == 0) pOut[(size_t)(tb + u) * pstr] = bal;
            ss += spk;
            spike = spk;
        }
        if (tc & 1){
            mcur = mnxt;
            const int wi = (tc >> 1) + 2;
            if (wi < NWORDS) mnxt = mkb[wi * HID + i];
        }
    }
    fr1[n * HID + i] = ss * (1.f / (float)T_STEPS);
}

// ---------------------------------------------------------------------------
// bf16 HMMA GEMM: C = S @ (Wh+Wl)^T, fp32 accum. A from 1-bit packed spikes
// expanded to bf16 in smem (bit-identical bytes); B hi/lo via cp.async.
// ---------------------------------------------------------------------------
__global__ void __launch_bounds__(256, 2)
gemm_bf16(int which)
{
    extern __shared__ char smem[];
    const uint8_t* __restrict__ Ap = (const uint8_t*)(which ? g_S2p : g_S1p);
    const __nv_bfloat16* __restrict__ Bh = which ? g_W3h : g_W2h;
    const __nv_bfloat16* __restrict__ Bl = which ? g_W3l : g_W2l;

    const uint32_t sb = smem_u32(smem);
    const int tid  = threadIdx.x;
    const int lane = tid & 31;
    const int wrp  = tid >> 5;
    const int wm   = wrp & 1;
    const int wn   = wrp >> 1;
    const int n0 = blockIdx.x * BN;
    const int m0 = blockIdx.y * BM;

    auto load_stage = [&](int st, int c){
        const uint32_t base = sb + (uint32_t)st * STAGEB;
        char* abase = smem + (size_t)st * STAGEB;
        #pragma unroll
        for (int i = 0; i < 4; ++i){
            const int q   = tid + 256 * i;
            const int row = q >> 3;
            const int kc  = q & 7;
            const uint32_t soff = (uint32_t)row * ROWB + (uint32_t)kc * 16u;
            const size_t gk = (size_t)c * BK + (size_t)kc * 8;
            const uint8_t bits = __ldg(Ap + (size_t)(m0 + row) * 64 + (size_t)c * 8 + kc);
            uint4 v;
            v.x = ((bits &   1u) ? 0x3F80u : 0u) | ((bits &   2u) ? 0x3F800000u : 0u);
            v.y = ((bits &   4u) ? 0x3F80u : 0u) | ((bits &   8u) ? 0x3F800000u : 0u);
            v.z = ((bits &  16u) ? 0x3F80u : 0u) | ((bits &  32u) ? 0x3F800000u : 0u);
            v.w = ((bits &  64u) ? 0x3F80u : 0u) | ((bits & 128u) ? 0x3F800000u : 0u);
            *(uint4*)(abase + soff) = v;
            cp16(base + TILEB + soff,     Bh + (size_t)(n0 + row) * KDIM + gk);
            cp16(base + 2u*TILEB + soff,  Bl + (size_t)(n0 + row) * KDIM + gk);
        }
        asm volatile("cp.async.commit_group;" ::: "memory");
    };

    float acc[4][4][4];
    #pragma unroll
    for (int mi = 0; mi < 4; ++mi)
        #pragma unroll
        for (int ni = 0; ni < 4; ++ni)
            #pragma unroll
            for (int q = 0; q < 4; ++q) acc[mi][ni][q] = 0.f;

    const uint32_t aOff = (uint32_t)(wm * 64 + (lane & 15)) * ROWB
                        + (uint32_t)((lane >> 4) << 3) * 2u;
    const uint32_t bOff = (uint32_t)(wn * 32 + ((lane >> 4) << 3) + (lane & 7)) * ROWB
                        + (uint32_t)(((lane >> 3) & 1) << 4);

    load_stage(0, 0);

    const int NC = KDIM / BK;   // 8
    for (int c = 0; c < NC; ++c){
        if (c + 1 < NC){
            load_stage((c + 1) & 1, c + 1);
            asm volatile("cp.async.wait_group 1;" ::: "memory");
        } else {
            asm volatile("cp.async.wait_group 0;" ::: "memory");
        }
        __syncthreads();

        const uint32_t base = sb + (uint32_t)(c & 1) * STAGEB;
        const uint32_t aB = base + aOff;
        const uint32_t hB = base + TILEB + bOff;
        const uint32_t lB = base + 2u*TILEB + bOff;

        #pragma unroll
        for (int k16 = 0; k16 < 4; ++k16){
            uint32_t a[4][4], bh[2][4], bl[2][4];
            #pragma unroll
            for (int mi = 0; mi < 4; ++mi)
                ldsm4(a[mi], aB + (uint32_t)(mi * 16) * ROWB + (uint32_t)k16 * 32u);
            #pragma unroll
            for (int p = 0; p < 2; ++p){
                ldsm4(bh[p], hB + (uint32_t)(p * 16) * ROWB + (uint32_t)k16 * 32u);
                ldsm4(bl[p], lB + (uint32_t)(p * 16) * ROWB + (uint32_t)k16 * 32u);
            }
            #pragma unroll
            for (int mi = 0; mi < 4; ++mi)
                #pragma unroll
                for (int ni = 0; ni < 4; ++ni){
                    mma_bf16(acc[mi][ni], a[mi], &bh[ni >> 1][(ni & 1) * 2]);
                    mma_bf16(acc[mi][ni], a[mi], &bl[ni >> 1][(ni & 1) * 2]);
                }
        }
        __syncthreads();
    }

    const int rbase = m0 + wm * 64 + (lane >> 2);
    const int cbase = n0 + wn * 32 + (lane & 3) * 2;
    #pragma unroll
    for (int mi = 0; mi < 4; ++mi){
        #pragma unroll
        for (int ni = 0; ni < 4; ++ni){
            float* p0 = g_C + (size_t)(rbase + mi * 16) * HID + cbase + ni * 8;
            float* p1 = p0 + 8 * HID;
            *(float2*)p0 = make_float2(acc[mi][ni][0], acc[mi][ni][1]);
            *(float2*)p1 = make_float2(acc[mi][ni][2], acc[mi][ni][3]);
        }
    }
}

// ---------------------------------------------------------------------------
// Layer-2/3 recurrence: bit-mask gating; layer==2 writes packed spikes.
// ---------------------------------------------------------------------------
__global__ void layerR_kernel(const float* __restrict__ bvec,
                              float* __restrict__ fr,
                              int maskSel, int layer)
{
    const int n = blockIdx.x;
    const int j = blockIdx.y * 128 + threadIdx.x;
    const int lane = threadIdx.x & 31;
    const float bj = bvec[j];
    const uint32_t* __restrict__ mkb = g_mkb[maskSel];
    const size_t cstr = (size_t)NBATCH * HID;
    const float* __restrict__ cPtr = g_C + (size_t)n * HID + j;
    uint32_t* __restrict__ pOut = g_S2p + (size_t)n * WPR
                                + (blockIdx.y * 4) + (threadIdx.x >> 5);
    const size_t pstr = (size_t)NBATCH * WPR;

    uint32_t mcur = mkb[j];
    uint32_t mnxt = mkb[HID + j];

    float cb[2][UNR];
    #pragma unroll
    for (int u = 0; u < UNR; ++u) cb[0][u] = cPtr[(size_t)u * cstr];

    float mem = 0.f, spike = 0.f, ss = 0.f;
    for (int tc = 0; tc < NBLK; ++tc){
        const int cur = tc & 1, nxt = cur ^ 1;
        const int tb = tc * UNR;
        if (tc + 1 < NBLK){
            #pragma unroll
            for (int u = 0; u < UNR; ++u)
                cb[nxt][u] = cPtr[(size_t)(tb + UNR + u) * cstr];
        }
        const uint32_t bits16 = (tc & 1) ? (mcur >> 16) : mcur;
        #pragma unroll
        for (int u = 0; u < UNR; ++u){
            const bool on = (bits16 >> u) & 1u;
            const float new_mem = mem * DECAY * (1.f - spike) + cb[cur][u] + bj;
            if (on) mem = new_mem;
            const float spk = (mem > THRESH && on) ? 1.f : 0.f;
            if (layer == 2){
                const unsigned bal = __ballot_sync(0xffffffffu, spk != 0.f);
                if (lane == 0) pOut[(size_t)(tb + u) * pstr] = bal;
            }
            ss += spk;
            spike = spk;
        }
        if (tc & 1){
            mcur = mnxt;
            const int wi = (tc >> 1) + 2;
            if (wi < NWORDS) mnxt = mkb[wi * HID + j];
        }
    }
    fr[n * HID + j] = ss * (1.f / (float)T_STEPS);
}

// ---------------------------------------------------------------------------
// Head: outputs[n][oc] = fr3[n] . W4[oc] + b4[oc]
// ---------------------------------------------------------------------------
__global__ void head_kernel(const float* __restrict__ fr3,
                            const float* __restrict__ W4,
                            const float* __restrict__ b4,
                            float* __restrict__ outputs)
{
    const int n = blockIdx.x;
    const int warp = threadIdx.x >> 5;
    const int lane = threadIdx.x & 31;
    const float* __restrict__ f = fr3 + (size_t)n * HID;
    const float* __restrict__ w = W4 + (size_t)warp * HID;
    float s = 0.f;
    for (int j = lane; j < HID; j += 32) s += f[j] * w[j];
#pragma unroll
    for (int o = 16; o > 0; o >>= 1) s += __shfl_xor_sync(0xffffffffu, s, o);
    if (lane == 0) outputs[n * OUTC + warp] = s + b4[warp];
}

// ---------------------------------------------------------------------------
// layer_fr[l] = mean(fr_l)
// ---------------------------------------------------------------------------
__global__ void lfr_kernel(const float* __restrict__ fr_all,
                           float* __restrict__ out3)
{
    const int l = blockIdx.x;
    const float* __restrict__ f = fr_all + (size_t)l * (NBATCH * HID);
    __shared__ float sh[256];
    float s = 0.f;
    for (int idx = threadIdx.x; idx < NBATCH * HID; idx += 256) s += f[idx];
    sh[threadIdx.x] = s;
    __syncthreads();
    for (int o = 128; o > 0; o >>= 1) {
        if (threadIdx.x < o) sh[threadIdx.x] += sh[threadIdx.x + o];
        __syncthreads();
    }
    if (threadIdx.x == 0) out3[l] = sh[0] * (1.f / (float)(NBATCH * HID));
}

// ---------------------------------------------------------------------------
// Launch (serial — proven fastest schedule)
// ---------------------------------------------------------------------------
extern "C" void kernel_launch(void* const* d_in, const int* in_sizes, int n_in,
                              void* d_out, int out_size)
{
    const float* x     = (const float*)d_in[0];
    const float* W1    = (const float*)d_in[1];
    const float* b1    = (const float*)d_in[2];
    const float* W2    = (const float*)d_in[3];
    const float* b2    = (const float*)d_in[4];
    const float* W3    = (const float*)d_in[5];
    const float* b3    = (const float*)d_in[6];
    const float* W4    = (const float*)d_in[7];
    const float* b4    = (const float*)d_in[8];
    const float* mask1 = (const float*)d_in[9];
    const float* mask2 = (const float*)d_in[10];
    const float* mask3 = (const float*)d_in[11];

    float* out     = (float*)d_out;
    float* outputs = out;
    float* fr1     = out + NBATCH * OUTC;
    float* fr2     = fr1 + NBATCH * HID;
    float* fr3     = fr2 + NBATCH * HID;
    float* lfr     = fr3 + NBATCH * HID;

    cudaFuncSetAttribute(gemm_bf16, cudaFuncAttributeMaxDynamicSharedMemorySize, GEMM_SMEM);

    dim3 gemm_grid(4, T_STEPS);       // x = bn, y = bm
    dim3 rec_grid(NBATCH, HID / 128); // 512 CTAs, 128 threads
    dim3 mb_grid(NWORDS, 3);

    maskbits_kernel<<<mb_grid, HID>>>(mask1, mask2, mask3);
    split_kernel<<<(HID*HID + 255)/256, 256>>>(W2, W3);
    layer1_kernel<<<rec_grid, 128>>>(x, W1, b1, fr1);
    gemm_bf16<<<gemm_grid, 256, GEMM_SMEM>>>(0);
    layerR_kernel<<<rec_grid, 128>>>(b2, fr2, 1, 2);
    gemm_bf16<<<gemm_grid, 256, GEMM_SMEM>>>(1);
    layerR_kernel<<<rec_grid, 128>>>(b3, fr3, 2, 3);
    head_kernel<<<NBATCH, 320>>>(fr3, W4, b4, outputs);
    lfr_kernel<<<3, 256>>>(fr1, lfr);
}

// round 12
// speedup vs baseline: 1.9347x; 1.0345x over previous
#include <cuda_runtime.h>
#include <cuda_bf16.h>
#include <cstdint>
#include <cstddef>

// Problem constants
#define T_STEPS 784
#define NBATCH  128
#define HID     512
#define OUTC    10
#define DECAY   0.2f
#define THRESH  0.5f
#define KDIM    512

// GEMM tiling
#define BM 128
#define BN 128
#define BK 64
#define ROWB 144u              // smem bytes per row: 64 bf16 (128B) + 16B pad
#define TILEB (128u * ROWB)    // 18432 B
#define STAGEB (3u * TILEB)    // A + Bh + Bl per stage
#define GEMM_SMEM (2u * STAGEB)

// Recurrence pipelining
#define UNR 16                 // 784 = 49 * 16
#define NBLK (T_STEPS / UNR)   // 49
#define NWORDS 25              // ceil(784/32)

// Packed spikes: 512 bits per (t,n) row = 16 words = 64 bytes
#define WPR 16
#define SEQ_ELEMS ((size_t)T_STEPS * NBATCH * HID)
__device__ uint32_t g_S1p[(size_t)T_STEPS * NBATCH * WPR];
__device__ uint32_t g_S2p[(size_t)T_STEPS * NBATCH * WPR];
__device__ float    g_C  [SEQ_ELEMS];        // GEMM output [t][n][j] fp32 dense
__device__ __nv_bfloat16 g_W2h[HID*HID], g_W2l[HID*HID];
__device__ __nv_bfloat16 g_W3h[HID*HID], g_W3l[HID*HID];
__device__ uint32_t g_mkb[3][NWORDS * HID];  // bit-packed masks: word w, neuron j

// ---------------------------------------------------------------------------
// PTX helpers
// ---------------------------------------------------------------------------
__device__ __forceinline__ uint32_t smem_u32(const void* p){
    uint32_t a;
    asm("{ .reg .u64 t; cvta.to.shared.u64 t, %1; cvt.u32.u64 %0, t; }" : "=r"(a) : "l"(p));
    return a;
}
__device__ __forceinline__ void cp16(uint32_t saddr, const void* gaddr){
    asm volatile("cp.async.cg.shared.global [%0], [%1], 16;" :: "r"(saddr), "l"(gaddr));
}
__device__ __forceinline__ void ldsm4(uint32_t* r, uint32_t addr){
    asm volatile("ldmatrix.sync.aligned.m8n8.x4.shared.b16 {%0,%1,%2,%3}, [%4];"
        : "=r"(r[0]), "=r"(r[1]), "=r"(r[2]), "=r"(r[3]) : "r"(addr));
}
__device__ __forceinline__ void mma_bf16(float* c, const uint32_t* a, const uint32_t* b){
    asm volatile(
        "mma.sync.aligned.m16n8k16.row.col.f32.bf16.bf16.f32 "
        "{%0,%1,%2,%3}, {%4,%5,%6,%7}, {%8,%9}, {%0,%1,%2,%3};"
        : "+f"(c[0]), "+f"(c[1]), "+f"(c[2]), "+f"(c[3])
        : "r"(a[0]), "r"(a[1]), "r"(a[2]), "r"(a[3]), "r"(b[0]), "r"(b[1]));
}

// ---------------------------------------------------------------------------
// Weight split: W -> hi(bf16) + lo(bf16)
// ---------------------------------------------------------------------------
__global__ void split_kernel(const float* __restrict__ W2, const float* __restrict__ W3){
    int idx = blockIdx.x * blockDim.x + threadIdx.x;
    if (idx < HID * HID){
        float w = W2[idx];
        __nv_bfloat16 h = __float2bfloat16(w);
        g_W2h[idx] = h;
        g_W2l[idx] = __float2bfloat16(w - __bfloat162float(h));
        w = W3[idx];
        h = __float2bfloat16(w);
        g_W3h[idx] = h;
        g_W3l[idx] = __float2bfloat16(w - __bfloat162float(h));
    }
}

// ---------------------------------------------------------------------------
// Mask bit-pack: [H][T] floats -> [NWORDS][H] words (bit b = t=32w+b on).
// ---------------------------------------------------------------------------
__global__ void maskbits_kernel(const float* __restrict__ m1,
                                const float* __restrict__ m2,
                                const float* __restrict__ m3)
{
    const int w = blockIdx.x;
    const int l = blockIdx.y;
    const int j = threadIdx.x;
    const float* __restrict__ src = (l == 0) ? m1 : (l == 1) ? m2 : m3;
    uint32_t bits = 0;
    #pragma unroll
    for (int b = 0; b < 32; ++b){
        const int t = w * 32 + b;
        if (t < T_STEPS && src[(size_t)j * T_STEPS + t] != 0.f) bits |= (1u << b);
    }
    g_mkb[l][w * HID + j] = bits;
}

// ---------------------------------------------------------------------------
// Layer-1 recurrence: bit-mask gating, shortened dependency chain,
// ballot-packed spike output.
// ---------------------------------------------------------------------------
__global__ void layer1_kernel(const float* __restrict__ x,
                              const float* __restrict__ W1,
                              const float* __restrict__ b1,
                              float* __restrict__ fr1)
{
    const int n = blockIdx.x;
    const int i = blockIdx.y * 128 + threadIdx.x;
    const int lane = threadIdx.x & 31;
    const float w = W1[i];
    const float b = b1[i];
    const float* __restrict__ xr = x + (size_t)n * T_STEPS;
    const uint32_t* __restrict__ mkb = g_mkb[0];
    uint32_t* __restrict__ pOut = g_S1p + (size_t)n * WPR
                                + (blockIdx.y * 4) + (threadIdx.x >> 5);
    const size_t pstr = (size_t)NBATCH * WPR;

    uint32_t mcur = mkb[i];
    uint32_t mnxt = mkb[HID + i];

    float xb[2][UNR];
    #pragma unroll
    for (int u = 0; u < UNR; ++u) xb[0][u] = xr[u];

    float mem = 0.f, spike = 0.f, ss = 0.f;
    for (int tc = 0; tc < NBLK; ++tc){
        const int cur = tc & 1, nxt = cur ^ 1;
        const int tb = tc * UNR;
        if (tc + 1 < NBLK){
            #pragma unroll
            for (int u = 0; u < UNR; ++u) xb[nxt][u] = xr[tb + UNR + u];
        }
        const uint32_t bits16 = (tc & 1) ? (mcur >> 16) : mcur;
        #pragma unroll
        for (int u = 0; u < UNR; ++u){
            const bool on = (bits16 >> u) & 1u;
            // spike in {0,1}: mem*DECAY*(1-spike) == (spike ? 0 : mem*DECAY)
            const float dec = (spike != 0.f) ? 0.f : mem * DECAY;
            const float nm = dec + xb[cur][u] * w + b;
            if (on) mem = nm;
            const float spk = (mem > THRESH && on) ? 1.f : 0.f;
            const unsigned bal = __ballot_sync(0xffffffffu, spk != 0.f);
            if (lane == 0) pOut[(size_t)(tb + u) * pstr] = bal;
            ss += spk;
            spike = spk;
        }
        if (tc & 1){
            mcur = mnxt;
            const int wi = (tc >> 1) + 2;
            if (wi < NWORDS) mnxt = mkb[wi * HID + i];
        }
    }
    fr1[n * HID + i] = ss * (1.f / (float)T_STEPS);
}

// ---------------------------------------------------------------------------
// bf16 HMMA GEMM: C = S @ (Wh+Wl)^T, fp32 accum. A from 1-bit packed spikes.
// load_stage: batched A-bit ldgs (MLP=4) -> cp.asyncs issued while in flight
// -> expansion stores last.
// ---------------------------------------------------------------------------
__global__ void __launch_bounds__(256, 2)
gemm_bf16(int which)
{
    extern __shared__ char smem[];
    const uint8_t* __restrict__ Ap = (const uint8_t*)(which ? g_S2p : g_S1p);
    const __nv_bfloat16* __restrict__ Bh = which ? g_W3h : g_W2h;
    const __nv_bfloat16* __restrict__ Bl = which ? g_W3l : g_W2l;

    const uint32_t sb = smem_u32(smem);
    const int tid  = threadIdx.x;
    const int lane = tid & 31;
    const int wrp  = tid >> 5;
    const int wm   = wrp & 1;
    const int wn   = wrp >> 1;
    const int n0 = blockIdx.x * BN;
    const int m0 = blockIdx.y * BM;

    auto load_stage = [&](int st, int c){
        const uint32_t base = sb + (uint32_t)st * STAGEB;
        char* abase = smem + (size_t)st * STAGEB;
        // 1) batch A-bit loads (independent, MLP=4)
        uint8_t bitsArr[4];
        #pragma unroll
        for (int i = 0; i < 4; ++i){
            const int q   = tid + 256 * i;
            const int row = q >> 3;
            const int kc  = q & 7;
            bitsArr[i] = __ldg(Ap + (size_t)(m0 + row) * 64 + (size_t)c * 8 + kc);
        }
        // 2) issue B cp.asyncs (do not depend on bits)
        #pragma unroll
        for (int i = 0; i < 4; ++i){
            const int q   = tid + 256 * i;
            const int row = q >> 3;
            const int kc  = q & 7;
            const uint32_t soff = (uint32_t)row * ROWB + (uint32_t)kc * 16u;
            const size_t gk = (size_t)c * BK + (size_t)kc * 8;
            cp16(base + TILEB + soff,     Bh + (size_t)(n0 + row) * KDIM + gk);
            cp16(base + 2u*TILEB + soff,  Bl + (size_t)(n0 + row) * KDIM + gk);
        }
        // 3) expand A bits -> bf16 smem
        #pragma unroll
        for (int i = 0; i < 4; ++i){
            const int q   = tid + 256 * i;
            const int row = q >> 3;
            const int kc  = q & 7;
            const uint32_t soff = (uint32_t)row * ROWB + (uint32_t)kc * 16u;
            const uint8_t bits = bitsArr[i];
            uint4 v;
            v.x = ((bits &   1u) ? 0x3F80u : 0u) | ((bits &   2u) ? 0x3F800000u : 0u);
            v.y = ((bits &   4u) ? 0x3F80u : 0u) | ((bits &   8u) ? 0x3F800000u : 0u);
            v.z = ((bits &  16u) ? 0x3F80u : 0u) | ((bits &  32u) ? 0x3F800000u : 0u);
            v.w = ((bits &  64u) ? 0x3F80u : 0u) | ((bits & 128u) ? 0x3F800000u : 0u);
            *(uint4*)(abase + soff) = v;
        }
        asm volatile("cp.async.commit_group;" ::: "memory");
    };

    float acc[4][4][4];
    #pragma unroll
    for (int mi = 0; mi < 4; ++mi)
        #pragma unroll
        for (int ni = 0; ni < 4; ++ni)
            #pragma unroll
            for (int q = 0; q < 4; ++q) acc[mi][ni][q] = 0.f;

    const uint32_t aOff = (uint32_t)(wm * 64 + (lane & 15)) * ROWB
                        + (uint32_t)((lane >> 4) << 3) * 2u;
    const uint32_t bOff = (uint32_t)(wn * 32 + ((lane >> 4) << 3) + (lane & 7)) * ROWB
                        + (uint32_t)(((lane >> 3) & 1) << 4);

    load_stage(0, 0);

    const int NC = KDIM / BK;   // 8
    for (int c = 0; c < NC; ++c){
        if (c + 1 < NC){
            load_stage((c + 1) & 1, c + 1);
            asm volatile("cp.async.wait_group 1;" ::: "memory");
        } else {
            asm volatile("cp.async.wait_group 0;" ::: "memory");
        }
        __syncthreads();

        const uint32_t base = sb + (uint32_t)(c & 1) * STAGEB;
        const uint32_t aB = base + aOff;
        const uint32_t hB = base + TILEB + bOff;
        const uint32_t lB = base + 2u*TILEB + bOff;

        #pragma unroll
        for (int k16 = 0; k16 < 4; ++k16){
            uint32_t a[4][4], bh[2][4], bl[2][4];
            #pragma unroll
            for (int mi = 0; mi < 4; ++mi)
                ldsm4(a[mi], aB + (uint32_t)(mi * 16) * ROWB + (uint32_t)k16 * 32u);
            #pragma unroll
            for (int p = 0; p < 2; ++p){
                ldsm4(bh[p], hB + (uint32_t)(p * 16) * ROWB + (uint32_t)k16 * 32u);
                ldsm4(bl[p], lB + (uint32_t)(p * 16) * ROWB + (uint32_t)k16 * 32u);
            }
            #pragma unroll
            for (int mi = 0; mi < 4; ++mi)
                #pragma unroll
                for (int ni = 0; ni < 4; ++ni){
                    mma_bf16(acc[mi][ni], a[mi], &bh[ni >> 1][(ni & 1) * 2]);
                    mma_bf16(acc[mi][ni], a[mi], &bl[ni >> 1][(ni & 1) * 2]);
                }
        }
        __syncthreads();
    }

    const int rbase = m0 + wm * 64 + (lane >> 2);
    const int cbase = n0 + wn * 32 + (lane & 3) * 2;
    #pragma unroll
    for (int mi = 0; mi < 4; ++mi){
        #pragma unroll
        for (int ni = 0; ni < 4; ++ni){
            float* p0 = g_C + (size_t)(rbase + mi * 16) * HID + cbase + ni * 8;
            float* p1 = p0 + 8 * HID;
            *(float2*)p0 = make_float2(acc[mi][ni][0], acc[mi][ni][1]);
            *(float2*)p1 = make_float2(acc[mi][ni][2], acc[mi][ni][3]);
        }
    }
}

// ---------------------------------------------------------------------------
// Layer-2/3 recurrence: bit-mask gating, shortened chain; layer==2 writes
// packed spikes.
// ---------------------------------------------------------------------------
__global__ void layerR_kernel(const float* __restrict__ bvec,
                              float* __restrict__ fr,
                              int maskSel, int layer)
{
    const int n = blockIdx.x;
    const int j = blockIdx.y * 128 + threadIdx.x;
    const int lane = threadIdx.x & 31;
    const float bj = bvec[j];
    const uint32_t* __restrict__ mkb = g_mkb[maskSel];
    const size_t cstr = (size_t)NBATCH * HID;
    const float* __restrict__ cPtr = g_C + (size_t)n * HID + j;
    uint32_t* __restrict__ pOut = g_S2p + (size_t)n * WPR
                                + (blockIdx.y * 4) + (threadIdx.x >> 5);
    const size_t pstr = (size_t)NBATCH * WPR;

    uint32_t mcur = mkb[j];
    uint32_t mnxt = mkb[HID + j];

    float cb[2][UNR];
    #pragma unroll
    for (int u = 0; u < UNR; ++u) cb[0][u] = cPtr[(size_t)u * cstr];

    float mem = 0.f, spike = 0.f, ss = 0.f;
    for (int tc = 0; tc < NBLK; ++tc){
        const int cur = tc & 1, nxt = cur ^ 1;
        const int tb = tc * UNR;
        if (tc + 1 < NBLK){
            #pragma unroll
            for (int u = 0; u < UNR; ++u)
                cb[nxt][u] = cPtr[(size_t)(tb + UNR + u) * cstr];
        }
        const uint32_t bits16 = (tc & 1) ? (mcur >> 16) : mcur;
        #pragma unroll
        for (int u = 0; u < UNR; ++u){
            const bool on = (bits16 >> u) & 1u;
            const float dec = (spike != 0.f) ? 0.f : mem * DECAY;
            const float nm = dec + cb[cur][u] + bj;
            if (on) mem = nm;
            const float spk = (mem > THRESH && on) ? 1.f : 0.f;
            if (layer == 2){
                const unsigned bal = __ballot_sync(0xffffffffu, spk != 0.f);
                if (lane == 0) pOut[(size_t)(tb + u) * pstr] = bal;
            }
            ss += spk;
            spike = spk;
        }
        if (tc & 1){
            mcur = mnxt;
            const int wi = (tc >> 1) + 2;
            if (wi < NWORDS) mnxt = mkb[wi * HID + j];
        }
    }
    fr[n * HID + j] = ss * (1.f / (float)T_STEPS);
}

// ---------------------------------------------------------------------------
// Fused head + layer_fr kernel.
// blocks 0..127: outputs[n] = fr3[n] @ W4^T + b4 (10 warps)
// blocks 128..130: layer_fr[l] = mean(fr_l)
// ---------------------------------------------------------------------------
__global__ void tail_kernel(const float* __restrict__ fr_all,
                            const float* __restrict__ W4,
                            const float* __restrict__ b4,
                            float* __restrict__ outputs,
                            float* __restrict__ out3)
{
    if (blockIdx.x < NBATCH){
        const int n = blockIdx.x;
        const int warp = threadIdx.x >> 5;
        const int lane = threadIdx.x & 31;
        if (warp >= OUTC) return;
        const float* __restrict__ f = fr_all + 2 * (NBATCH * HID) + (size_t)n * HID;
        const float* __restrict__ w = W4 + (size_t)warp * HID;
        float s = 0.f;
        for (int j = lane; j < HID; j += 32) s += f[j] * w[j];
        #pragma unroll
        for (int o = 16; o > 0; o >>= 1) s += __shfl_xor_sync(0xffffffffu, s, o);
        if (lane == 0) outputs[n * OUTC + warp] = s + b4[warp];
    } else {
        const int l = blockIdx.x - NBATCH;
        const float* __restrict__ f = fr_all + (size_t)l * (NBATCH * HID);
        __shared__ float sh[320];
        float s = 0.f;
        for (int idx = threadIdx.x; idx < NBATCH * HID; idx += 320) s += f[idx];
        sh[threadIdx.x] = s;
        __syncthreads();
        if (threadIdx.x < 64){
            float v = sh[threadIdx.x];
            for (int o = threadIdx.x + 64; o < 320; o += 64) v += sh[o];
            sh[threadIdx.x] = v;
        }
        __syncthreads();
        if (threadIdx.x == 0){
            float v = 0.f;
            for (int o = 0; o < 64; ++o) v += sh[o];
            out3[l] = v * (1.f / (float)(NBATCH * HID));
        }
    }
}

// ---------------------------------------------------------------------------
// Launch (serial — proven fastest schedule)
// ---------------------------------------------------------------------------
extern "C" void kernel_launch(void* const* d_in, const int* in_sizes, int n_in,
                              void* d_out, int out_size)
{
    const float* x     = (const float*)d_in[0];
    const float* W1    = (const float*)d_in[1];
    const float* b1    = (const float*)d_in[2];
    const float* W2    = (const float*)d_in[3];
    const float* b2    = (const float*)d_in[4];
    const float* W3    = (const float*)d_in[5];
    const float* b3    = (const float*)d_in[6];
    const float* W4    = (const float*)d_in[7];
    const float* b4    = (const float*)d_in[8];
    const float* mask1 = (const float*)d_in[9];
    const float* mask2 = (const float*)d_in[10];
    const float* mask3 = (const float*)d_in[11];

    float* out     = (float*)d_out;
    float* outputs = out;
    float* fr1     = out + NBATCH * OUTC;
    float* fr2     = fr1 + NBATCH * HID;
    float* fr3     = fr2 + NBATCH * HID;
    float* lfr     = fr3 + NBATCH * HID;

    cudaFuncSetAttribute(gemm_bf16, cudaFuncAttributeMaxDynamicSharedMemorySize, GEMM_SMEM);

    dim3 gemm_grid(4, T_STEPS);       // x = bn, y = bm
    dim3 rec_grid(NBATCH, HID / 128); // 512 CTAs, 128 threads
    dim3 mb_grid(NWORDS, 3);

    maskbits_kernel<<<mb_grid, HID>>>(mask1, mask2, mask3);
    split_kernel<<<(HID*HID + 255)/256, 256>>>(W2, W3);
    layer1_kernel<<<rec_grid, 128>>>(x, W1, b1, fr1);
    gemm_bf16<<<gemm_grid, 256, GEMM_SMEM>>>(0);
    layerR_kernel<<<rec_grid, 128>>>(b2, fr2, 1, 2);
    gemm_bf16<<<gemm_grid, 256, GEMM_SMEM>>>(1);
    layerR_kernel<<<rec_grid, 128>>>(b3, fr3, 2, 3);
    tail_kernel<<<NBATCH + 3, 320>>>(fr1, W4, b4, outputs, lfr);
}

// round 13
// speedup vs baseline: 2.1932x; 1.1336x over previous
#include <cuda_runtime.h>
#include <cuda_bf16.h>
#include <cstdint>
#include <cstddef>

// Problem constants
#define T_STEPS 784
#define NBATCH  128
#define HID     512
#define OUTC    10
#define DECAY   0.2f
#define THRESH  0.5f
#define KDIM    512

// GEMM tiling
#define BM 128
#define BN 128
#define BK 64
#define ROWB 144u              // smem bytes per row: 64 bf16 (128B) + 16B pad
#define TILEB (128u * ROWB)    // 18432 B
#define STAGEB (3u * TILEB)    // A + Bh + Bl per stage
#define GEMM_SMEM (2u * STAGEB)

// Recurrence pipelining
#define UNR 16                 // 784 = 49 * 16
#define NBLK (T_STEPS / UNR)   // 49
#define NWORDS 25              // ceil(784/32)

// Packed spikes: 512 bits per (t,n) row = 16 words = 64 bytes
#define WPR 16
#define SEQ_ELEMS ((size_t)T_STEPS * NBATCH * HID)
__device__ uint32_t g_S1p[(size_t)T_STEPS * NBATCH * WPR];
__device__ uint32_t g_S2p[(size_t)T_STEPS * NBATCH * WPR];
__device__ float    g_C  [SEQ_ELEMS];        // GEMM output [t][n][j] fp32 dense
__device__ __nv_bfloat16 g_W2h[HID*HID], g_W2l[HID*HID];
__device__ __nv_bfloat16 g_W3h[HID*HID], g_W3l[HID*HID];
__device__ uint32_t g_mkb[3][NWORDS * HID];  // bit-packed masks: word w, neuron j

// ---------------------------------------------------------------------------
// PTX helpers
// ---------------------------------------------------------------------------
__device__ __forceinline__ uint32_t smem_u32(const void* p){
    uint32_t a;
    asm("{ .reg .u64 t; cvta.to.shared.u64 t, %1; cvt.u32.u64 %0, t; }" : "=r"(a) : "l"(p));
    return a;
}
__device__ __forceinline__ void cp16(uint32_t saddr, const void* gaddr){
    asm volatile("cp.async.cg.shared.global [%0], [%1], 16;" :: "r"(saddr), "l"(gaddr));
}
__device__ __forceinline__ void ldsm4(uint32_t* r, uint32_t addr){
    asm volatile("ldmatrix.sync.aligned.m8n8.x4.shared.b16 {%0,%1,%2,%3}, [%4];"
        : "=r"(r[0]), "=r"(r[1]), "=r"(r[2]), "=r"(r[3]) : "r"(addr));
}
__device__ __forceinline__ void mma_bf16(float* c, const uint32_t* a, const uint32_t* b){
    asm volatile(
        "mma.sync.aligned.m16n8k16.row.col.f32.bf16.bf16.f32 "
        "{%0,%1,%2,%3}, {%4,%5,%6,%7}, {%8,%9}, {%0,%1,%2,%3};"
        : "+f"(c[0]), "+f"(c[1]), "+f"(c[2]), "+f"(c[3])
        : "r"(a[0]), "r"(a[1]), "r"(a[2]), "r"(a[3]), "r"(b[0]), "r"(b[1]));
}

// ---------------------------------------------------------------------------
// Weight split: W -> hi(bf16) + lo(bf16)
// ---------------------------------------------------------------------------
__global__ void split_kernel(const float* __restrict__ W2, const float* __restrict__ W3){
    int idx = blockIdx.x * blockDim.x + threadIdx.x;
    if (idx < HID * HID){
        float w = W2[idx];
        __nv_bfloat16 h = __float2bfloat16(w);
        g_W2h[idx] = h;
        g_W2l[idx] = __float2bfloat16(w - __bfloat162float(h));
        w = W3[idx];
        h = __float2bfloat16(w);
        g_W3h[idx] = h;
        g_W3l[idx] = __float2bfloat16(w - __bfloat162float(h));
    }
}

// ---------------------------------------------------------------------------
// Mask bit-pack: [H][T] floats -> [NWORDS][H] words (bit b = t=32w+b on).
// ---------------------------------------------------------------------------
__global__ void maskbits_kernel(const float* __restrict__ m1,
                                const float* __restrict__ m2,
                                const float* __restrict__ m3)
{
    const int w = blockIdx.x;
    const int l = blockIdx.y;
    const int j = threadIdx.x;
    const float* __restrict__ src = (l == 0) ? m1 : (l == 1) ? m2 : m3;
    uint32_t bits = 0;
    #pragma unroll
    for (int b = 0; b < 32; ++b){
        const int t = w * 32 + b;
        if (t < T_STEPS && src[(size_t)j * T_STEPS + t] != 0.f) bits |= (1u << b);
    }
    g_mkb[l][w * HID + j] = bits;
}

// ---------------------------------------------------------------------------
// Layer-1 recurrence: bit-mask gating, shortened dependency chain,
// ballot-packed spike output.
// ---------------------------------------------------------------------------
__global__ void layer1_kernel(const float* __restrict__ x,
                              const float* __restrict__ W1,
                              const float* __restrict__ b1,
                              float* __restrict__ fr1)
{
    const int n = blockIdx.x;
    const int i = blockIdx.y * 128 + threadIdx.x;
    const int lane = threadIdx.x & 31;
    const float w = W1[i];
    const float b = b1[i];
    const float* __restrict__ xr = x + (size_t)n * T_STEPS;
    const uint32_t* __restrict__ mkb = g_mkb[0];
    uint32_t* __restrict__ pOut = g_S1p + (size_t)n * WPR
                                + (blockIdx.y * 4) + (threadIdx.x >> 5);
    const size_t pstr = (size_t)NBATCH * WPR;

    uint32_t mcur = mkb[i];
    uint32_t mnxt = mkb[HID + i];

    float xb[2][UNR];
    #pragma unroll
    for (int u = 0; u < UNR; ++u) xb[0][u] = xr[u];

    float mem = 0.f, spike = 0.f, ss = 0.f;
    for (int tc = 0; tc < NBLK; ++tc){
        const int cur = tc & 1, nxt = cur ^ 1;
        const int tb = tc * UNR;
        if (tc + 1 < NBLK){
            #pragma unroll
            for (int u = 0; u < UNR; ++u) xb[nxt][u] = xr[tb + UNR + u];
        }
        const uint32_t bits16 = (tc & 1) ? (mcur >> 16) : mcur;
        #pragma unroll
        for (int u = 0; u < UNR; ++u){
            const bool on = (bits16 >> u) & 1u;
            const float dec = (spike != 0.f) ? 0.f : mem * DECAY;
            const float nm = dec + xb[cur][u] * w + b;
            if (on) mem = nm;
            const float spk = (mem > THRESH && on) ? 1.f : 0.f;
            const unsigned bal = __ballot_sync(0xffffffffu, spk != 0.f);
            if (lane == 0) pOut[(size_t)(tb + u) * pstr] = bal;
            ss += spk;
            spike = spk;
        }
        if (tc & 1){
            mcur = mnxt;
            const int wi = (tc >> 1) + 2;
            if (wi < NWORDS) mnxt = mkb[wi * HID + i];
        }
    }
    fr1[n * HID + i] = ss * (1.f / (float)T_STEPS);
}

// ---------------------------------------------------------------------------
// bf16 HMMA GEMM: C = S @ (Wh+Wl)^T, fp32 accum. A from 1-bit packed spikes.
// (UNCHANGED from R12 — protects the rel_err invariant.)
// ---------------------------------------------------------------------------
__global__ void __launch_bounds__(256, 2)
gemm_bf16(int which)
{
    extern __shared__ char smem[];
    const uint8_t* __restrict__ Ap = (const uint8_t*)(which ? g_S2p : g_S1p);
    const __nv_bfloat16* __restrict__ Bh = which ? g_W3h : g_W2h;
    const __nv_bfloat16* __restrict__ Bl = which ? g_W3l : g_W2l;

    const uint32_t sb = smem_u32(smem);
    const int tid  = threadIdx.x;
    const int lane = tid & 31;
    const int wrp  = tid >> 5;
    const int wm   = wrp & 1;
    const int wn   = wrp >> 1;
    const int n0 = blockIdx.x * BN;
    const int m0 = blockIdx.y * BM;

    auto load_stage = [&](int st, int c){
        const uint32_t base = sb + (uint32_t)st * STAGEB;
        char* abase = smem + (size_t)st * STAGEB;
        uint8_t bitsArr[4];
        #pragma unroll
        for (int i = 0; i < 4; ++i){
            const int q   = tid + 256 * i;
            const int row = q >> 3;
            const int kc  = q & 7;
            bitsArr[i] = __ldg(Ap + (size_t)(m0 + row) * 64 + (size_t)c * 8 + kc);
        }
        #pragma unroll
        for (int i = 0; i < 4; ++i){
            const int q   = tid + 256 * i;
            const int row = q >> 3;
            const int kc  = q & 7;
            const uint32_t soff = (uint32_t)row * ROWB + (uint32_t)kc * 16u;
            const size_t gk = (size_t)c * BK + (size_t)kc * 8;
            cp16(base + TILEB + soff,     Bh + (size_t)(n0 + row) * KDIM + gk);
            cp16(base + 2u*TILEB + soff,  Bl + (size_t)(n0 + row) * KDIM + gk);
        }
        #pragma unroll
        for (int i = 0; i < 4; ++i){
            const int q   = tid + 256 * i;
            const int row = q >> 3;
            const int kc  = q & 7;
            const uint32_t soff = (uint32_t)row * ROWB + (uint32_t)kc * 16u;
            const uint8_t bits = bitsArr[i];
            uint4 v;
            v.x = ((bits &   1u) ? 0x3F80u : 0u) | ((bits &   2u) ? 0x3F800000u : 0u);
            v.y = ((bits &   4u) ? 0x3F80u : 0u) | ((bits &   8u) ? 0x3F800000u : 0u);
            v.z = ((bits &  16u) ? 0x3F80u : 0u) | ((bits &  32u) ? 0x3F800000u : 0u);
            v.w = ((bits &  64u) ? 0x3F80u : 0u) | ((bits & 128u) ? 0x3F800000u : 0u);
            *(uint4*)(abase + soff) = v;
        }
        asm volatile("cp.async.commit_group;" ::: "memory");
    };

    float acc[4][4][4];
    #pragma unroll
    for (int mi = 0; mi < 4; ++mi)
        #pragma unroll
        for (int ni = 0; ni < 4; ++ni)
            #pragma unroll
            for (int q = 0; q < 4; ++q) acc[mi][ni][q] = 0.f;

    const uint32_t aOff = (uint32_t)(wm * 64 + (lane & 15)) * ROWB
                        + (uint32_t)((lane >> 4) << 3) * 2u;
    const uint32_t bOff = (uint32_t)(wn * 32 + ((lane >> 4) << 3) + (lane & 7)) * ROWB
                        + (uint32_t)(((lane >> 3) & 1) << 4);

    load_stage(0, 0);

    const int NC = KDIM / BK;   // 8
    for (int c = 0; c < NC; ++c){
        if (c + 1 < NC){
            load_stage((c + 1) & 1, c + 1);
            asm volatile("cp.async.wait_group 1;" ::: "memory");
        } else {
            asm volatile("cp.async.wait_group 0;" ::: "memory");
        }
        __syncthreads();

        const uint32_t base = sb + (uint32_t)(c & 1) * STAGEB;
        const uint32_t aB = base + aOff;
        const uint32_t hB = base + TILEB + bOff;
        const uint32_t lB = base + 2u*TILEB + bOff;

        #pragma unroll
        for (int k16 = 0; k16 < 4; ++k16){
            uint32_t a[4][4], bh[2][4], bl[2][4];
            #pragma unroll
            for (int mi = 0; mi < 4; ++mi)
                ldsm4(a[mi], aB + (uint32_t)(mi * 16) * ROWB + (uint32_t)k16 * 32u);
            #pragma unroll
            for (int p = 0; p < 2; ++p){
                ldsm4(bh[p], hB + (uint32_t)(p * 16) * ROWB + (uint32_t)k16 * 32u);
                ldsm4(bl[p], lB + (uint32_t)(p * 16) * ROWB + (uint32_t)k16 * 32u);
            }
            #pragma unroll
            for (int mi = 0; mi < 4; ++mi)
                #pragma unroll
                for (int ni = 0; ni < 4; ++ni){
                    mma_bf16(acc[mi][ni], a[mi], &bh[ni >> 1][(ni & 1) * 2]);
                    mma_bf16(acc[mi][ni], a[mi], &bl[ni >> 1][(ni & 1) * 2]);
                }
        }
        __syncthreads();
    }

    const int rbase = m0 + wm * 64 + (lane >> 2);
    const int cbase = n0 + wn * 32 + (lane & 3) * 2;
    #pragma unroll
    for (int mi = 0; mi < 4; ++mi){
        #pragma unroll
        for (int ni = 0; ni < 4; ++ni){
            float* p0 = g_C + (size_t)(rbase + mi * 16) * HID + cbase + ni * 8;
            float* p1 = p0 + 8 * HID;
            *(float2*)p0 = make_float2(acc[mi][ni][0], acc[mi][ni][1]);
            *(float2*)p1 = make_float2(acc[mi][ni][2], acc[mi][ni][3]);
        }
    }
}

// ---------------------------------------------------------------------------
// Layer-2/3 recurrence: bit-mask gating; 3-buffer (2-blocks-ahead) c-prefetch
// to cover loaded-DRAM latency. Arithmetic identical to R12.
// ---------------------------------------------------------------------------
__global__ void layerR_kernel(const float* __restrict__ bvec,
                              float* __restrict__ fr,
                              int maskSel, int layer)
{
    const int n = blockIdx.x;
    const int j = blockIdx.y * 128 + threadIdx.x;
    const int lane = threadIdx.x & 31;
    const float bj = bvec[j];
    const uint32_t* __restrict__ mkb = g_mkb[maskSel];
    const size_t cstr = (size_t)NBATCH * HID;
    const float* __restrict__ cPtr = g_C + (size_t)n * HID + j;
    uint32_t* __restrict__ pOut = g_S2p + (size_t)n * WPR
                                + (blockIdx.y * 4) + (threadIdx.x >> 5);
    const size_t pstr = (size_t)NBATCH * WPR;

    uint32_t mcur = mkb[j];
    uint32_t mnxt = mkb[HID + j];

    float cb[3][UNR];
    #pragma unroll
    for (int u = 0; u < UNR; ++u) cb[0][u] = cPtr[(size_t)u * cstr];
    #pragma unroll
    for (int u = 0; u < UNR; ++u) cb[1][u] = cPtr[(size_t)(UNR + u) * cstr];

    float mem = 0.f, spike = 0.f, ss = 0.f;
    #pragma unroll 3
    for (int tc = 0; tc < NBLK; ++tc){
        const int s0 = tc % 3;
        const int tb = tc * UNR;
        if (tc + 2 < NBLK){
            const int s2 = (tc + 2) % 3;
            #pragma unroll
            for (int u = 0; u < UNR; ++u)
                cb[s2][u] = cPtr[(size_t)(tb + 2 * UNR + u) * cstr];
        }
        const uint32_t bits16 = (tc & 1) ? (mcur >> 16) : mcur;
        #pragma unroll
        for (int u = 0; u < UNR; ++u){
            const bool on = (bits16 >> u) & 1u;
            const float dec = (spike != 0.f) ? 0.f : mem * DECAY;
            const float nm = dec + cb[s0][u] + bj;
            if (on) mem = nm;
            const float spk = (mem > THRESH && on) ? 1.f : 0.f;
            if (layer == 2){
                const unsigned bal = __ballot_sync(0xffffffffu, spk != 0.f);
                if (lane == 0) pOut[(size_t)(tb + u) * pstr] = bal;
            }
            ss += spk;
            spike = spk;
        }
        if (tc & 1){
            mcur = mnxt;
            const int wi = (tc >> 1) + 2;
            if (wi < NWORDS) mnxt = mkb[wi * HID + j];
        }
    }
    fr[n * HID + j] = ss * (1.f / (float)T_STEPS);
}

// ---------------------------------------------------------------------------
// Fused head + layer_fr kernel.
// ---------------------------------------------------------------------------
__global__ void tail_kernel(const float* __restrict__ fr_all,
                            const float* __restrict__ W4,
                            const float* __restrict__ b4,
                            float* __restrict__ outputs,
                            float* __restrict__ out3)
{
    if (blockIdx.x < NBATCH){
        const int n = blockIdx.x;
        const int warp = threadIdx.x >> 5;
        const int lane = threadIdx.x & 31;
        if (warp >= OUTC) return;
        const float* __restrict__ f = fr_all + 2 * (NBATCH * HID) + (size_t)n * HID;
        const float* __restrict__ w = W4 + (size_t)warp * HID;
        float s = 0.f;
        for (int j = lane; j < HID; j += 32) s += f[j] * w[j];
        #pragma unroll
        for (int o = 16; o > 0; o >>= 1) s += __shfl_xor_sync(0xffffffffu, s, o);
        if (lane == 0) outputs[n * OUTC + warp] = s + b4[warp];
    } else {
        const int l = blockIdx.x - NBATCH;
        const float* __restrict__ f = fr_all + (size_t)l * (NBATCH * HID);
        __shared__ float sh[320];
        float s = 0.f;
        for (int idx = threadIdx.x; idx < NBATCH * HID; idx += 320) s += f[idx];
        sh[threadIdx.x] = s;
        __syncthreads();
        if (threadIdx.x < 64){
            float v = sh[threadIdx.x];
            for (int o = threadIdx.x + 64; o < 320; o += 64) v += sh[o];
            sh[threadIdx.x] = v;
        }
        __syncthreads();
        if (threadIdx.x == 0){
            float v = 0.f;
            for (int o = 0; o < 64; ++o) v += sh[o];
            out3[l] = v * (1.f / (float)(NBATCH * HID));
        }
    }
}

// ---------------------------------------------------------------------------
// Launch: serial main chain; split_kernel overlapped on a side stream
// (only GEMM-1 depends on it).
// ---------------------------------------------------------------------------
extern "C" void kernel_launch(void* const* d_in, const int* in_sizes, int n_in,
                              void* d_out, int out_size)
{
    const float* x     = (const float*)d_in[0];
    const float* W1    = (const float*)d_in[1];
    const float* b1    = (const float*)d_in[2];
    const float* W2    = (const float*)d_in[3];
    const float* b2    = (const float*)d_in[4];
    const float* W3    = (const float*)d_in[5];
    const float* b3    = (const float*)d_in[6];
    const float* W4    = (const float*)d_in[7];
    const float* b4    = (const float*)d_in[8];
    const float* mask1 = (const float*)d_in[9];
    const float* mask2 = (const float*)d_in[10];
    const float* mask3 = (const float*)d_in[11];

    float* out     = (float*)d_out;
    float* outputs = out;
    float* fr1     = out + NBATCH * OUTC;
    float* fr2     = fr1 + NBATCH * HID;
    float* fr3     = fr2 + NBATCH * HID;
    float* lfr     = fr3 + NBATCH * HID;

    static cudaStream_t sB = nullptr;
    static cudaEvent_t evF, evS;
    if (!sB){
        cudaStreamCreateWithFlags(&sB, cudaStreamNonBlocking);
        cudaEventCreateWithFlags(&evF, cudaEventDisableTiming);
        cudaEventCreateWithFlags(&evS, cudaEventDisableTiming);
        cudaFuncSetAttribute(gemm_bf16, cudaFuncAttributeMaxDynamicSharedMemorySize, GEMM_SMEM);
    }

    dim3 gemm_grid(4, T_STEPS);       // x = bn, y = bm
    dim3 rec_grid(NBATCH, HID / 128); // 512 CTAs, 128 threads
    dim3 mb_grid(NWORDS, 3);

    // Fork: weight split on side stream (needed only by GEMM-1)
    cudaEventRecord(evF, 0);
    cudaStreamWaitEvent(sB, evF, 0);
    split_kernel<<<(HID*HID + 255)/256, 256, 0, sB>>>(W2, W3);
    cudaEventRecord(evS, sB);

    maskbits_kernel<<<mb_grid, HID>>>(mask1, mask2, mask3);
    layer1_kernel<<<rec_grid, 128>>>(x, W1, b1, fr1);
    cudaStreamWaitEvent(0, evS, 0);   // join before GEMM-1
    gemm_bf16<<<gemm_grid, 256, GEMM_SMEM>>>(0);
    layerR_kernel<<<rec_grid, 128>>>(b2, fr2, 1, 2);
    gemm_bf16<<<gemm_grid, 256, GEMM_SMEM>>>(1);
    layerR_kernel<<<rec_grid, 128>>>(b3, fr3, 2, 3);
    tail_kernel<<<NBATCH + 3, 320>>>(fr1, W4, b4, outputs, lfr);
}